// round 5
// baseline (speedup 1.0000x reference)
#include <cuda_runtime.h>
#include <math.h>

#define N_NODES_MAX 100000
#define N_EDGES_MAX 1600000

typedef unsigned long long u64;
typedef ulonglong2 u64x2;

// -------- scratch (static __device__; no allocation at launch time) --------
__device__ float4 g_emb4[N_EDGES_MAX];     // (em0, em1, em2, unused)
__device__ float4 g_pos4[N_NODES_MAX];
__device__ float4 g_feat4[N_NODES_MAX];
__device__ float4 g_xA[N_NODES_MAX];
__device__ float4 g_xB[N_NODES_MAX];
__device__ float4 g_xC[N_NODES_MAX];
__device__ float  g_M[128];   // fused fc3_w2 x conv_w : [k=16][u=4][c=2], CCORE folded

// -------- constants (all e3nn normalization folded) --------
#define EMBC  (1.14136f * 7.38905609893065f * 1.7320508075688772f)
#define C1    (1.41421356237f / 48.0f)
#define CCORE (1.41421356237f / (1.7320508075688772f * 32.0f))

// -------- packed f32x2 helpers --------
__device__ __forceinline__ u64 pack2(float x, float y) {
    u64 r; asm("mov.b64 %0, {%1, %2};" : "=l"(r) : "f"(x), "f"(y)); return r;
}
__device__ __forceinline__ void unpack2(u64 v, float& x, float& y) {
    asm("mov.b64 {%0, %1}, %2;" : "=f"(x), "=f"(y) : "l"(v));
}
__device__ __forceinline__ void fma2(u64& d, u64 a, u64 b) {
    asm("fma.rn.f32x2 %0, %1, %2, %0;" : "+l"(d) : "l"(a), "l"(b));
}
__device__ __forceinline__ u64 mul2(u64 a, u64 b) {
    u64 d; asm("mul.rn.f32x2 %0, %1, %2;" : "=l"(d) : "l"(a), "l"(b)); return d;
}

// -------- vectorized global reductions (sm_90+) --------
__device__ __forceinline__ void red_add_v4(float4* addr, float a, float b, float c, float d) {
    asm volatile("red.global.add.v4.f32 [%0], {%1, %2, %3, %4};"
                 :: "l"(addr), "f"(a), "f"(b), "f"(c), "f"(d) : "memory");
}
__device__ __forceinline__ void red_add_v2(float* addr, float a, float b) {
    asm volatile("red.global.add.v2.f32 [%0], {%1, %2};"
                 :: "l"(addr), "f"(a), "f"(b) : "memory");
}

// ============================================================================
// prep: pack pos/feat into float4 tables, zero xA/xB, write bias into out
__global__ void __launch_bounds__(256) prep_kernel(
    const float* __restrict__ pos, const float* __restrict__ feat,
    const float* __restrict__ conv_b, float* __restrict__ out, int n)
{
    int i = blockIdx.x * 256 + threadIdx.x;
    if (i >= n) return;
    g_pos4[i]  = make_float4(pos[3 * i], pos[3 * i + 1], pos[3 * i + 2], 0.f);
    g_feat4[i] = make_float4(feat[3 * i], feat[3 * i + 1], feat[3 * i + 2], 0.f);
    g_xA[i] = make_float4(0.f, 0.f, 0.f, 0.f);
    g_xB[i] = make_float4(0.f, 0.f, 0.f, 0.f);
    ((float2*)out)[i] = make_float2(conv_b[0], conv_b[1]);
}

// M[k,u,c] = CCORE * sum_w fc3_w2[k, u*16+w] * conv_w[c, w]
__global__ void mprep_kernel(const float* __restrict__ fc3_w2, const float* __restrict__ conv_w) {
    int t = threadIdx.x;            // 128
    int k = t >> 3, u = (t >> 1) & 3, c = t & 1;
    float s = 0.f;
#pragma unroll
    for (int w = 0; w < 16; w++)
        s += fc3_w2[k * 64 + u * 16 + w] * conv_w[c * 16 + w];
    g_M[t] = CCORE * s;
}

// -------- packed r[16] for TWO edges, sharing the 12 weight LDS ----------
__device__ __forceinline__ void compute_r_pairs2(
    const u64* sW1u,
    float a0x, float a0y, float a0z,
    float a1x, float a1y, float a1z,
    float* rlo0, float* rhi0, float* rlo1, float* rhi1)
{
    u64 e00 = pack2(a0x, a0x), e01 = pack2(a0y, a0y), e02 = pack2(a0z, a0z);
    u64 e10 = pack2(a1x, a1x), e11 = pack2(a1y, a1y), e12 = pack2(a1z, a1z);
    const u64x2* w0 = (const u64x2*)(sW1u);
    const u64x2* w1 = (const u64x2*)(sW1u + 8);
    const u64x2* w2 = (const u64x2*)(sW1u + 16);
#pragma unroll
    for (int q = 0; q < 4; q++) {
        u64x2 a = w0[q], b = w1[q], c = w2[q];
        u64 v0 = mul2(e00, a.x), v1 = mul2(e00, a.y);
        fma2(v0, e01, b.x); fma2(v1, e01, b.y);
        fma2(v0, e02, c.x); fma2(v1, e02, c.y);
        u64 u0 = mul2(e10, a.x), u1 = mul2(e10, a.y);
        fma2(u0, e11, b.x); fma2(u1, e11, b.y);
        fma2(u0, e12, c.x); fma2(u1, e12, c.y);
        float p, r;
        unpack2(v0, p, r); rlo0[2*q] = fmaxf(p, 0.f);   rhi0[2*q] = fmaxf(r, 0.f);
        unpack2(v1, p, r); rlo0[2*q+1] = fmaxf(p, 0.f); rhi0[2*q+1] = fmaxf(r, 0.f);
        unpack2(u0, p, r); rlo1[2*q] = fmaxf(p, 0.f);   rhi1[2*q] = fmaxf(r, 0.f);
        unpack2(u1, p, r); rlo1[2*q+1] = fmaxf(p, 0.f); rhi1[2*q+1] = fmaxf(r, 0.f);
    }
}

// ============================================================================
// conv1: 2 edges/thread; emb precompute + r + 16x12 GEMM + msg scatter
__global__ void __launch_bounds__(256, 2) conv1_kernel(
    const int* __restrict__ esrc, const int* __restrict__ edst,
    const float* __restrict__ w1, const float* __restrict__ w2,
    float4* __restrict__ xout, int E)
{
    __shared__ __align__(16) u64 sW1u[24];
    __shared__ __align__(16) u64 sW2u[96];   // [k*6 + jp], C1 folded
    int t = threadIdx.x;
    if (t < 24) {
        int i = t / 8, kp = t % 8;
        sW1u[t] = pack2(w1[i * 16 + 2 * kp], w1[i * 16 + 2 * kp + 1]);
    }
    if (t < 96) {
        int k = t / 6, jp = t % 6;
        sW2u[t] = pack2(C1 * w2[k * 12 + 2 * jp], C1 * w2[k * 12 + 2 * jp + 1]);
    }
    __syncthreads();

    int base = blockIdx.x * 512;
    int e0 = base + t, e1 = base + 256 + t;
    bool v0 = e0 < E, v1 = e1 < E;
    int s0 = 0, d0 = 0, s1 = 0, d1 = 0;
    if (v0) { s0 = esrc[e0]; d0 = edst[e0]; }
    if (v1) { s1 = esrc[e1]; d1 = edst[e1]; }

    float4 ps0 = g_pos4[s0], pd0 = g_pos4[d0], f0 = g_feat4[s0];
    float4 ps1 = g_pos4[s1], pd1 = g_pos4[d1], f1 = g_feat4[s1];

    float em0[3], em1[3];
    {
        float dx = pd0.x - ps0.x, dy = pd0.y - ps0.y, dz = pd0.z - ps0.z;
        float dist = sqrtf(dx * dx + dy * dy + dz * dz);
#pragma unroll
        for (int i = 0; i < 3; i++) {
            float tt = (dist - 0.75f * (float)(i + 1)) * (1.0f / 0.75f);
            float q = 1.0f - tt * tt;
            em0[i] = (q > 0.0f) ? EMBC * __expf(__fdividef(-2.0f, q)) : 0.0f;
        }
    }
    {
        float dx = pd1.x - ps1.x, dy = pd1.y - ps1.y, dz = pd1.z - ps1.z;
        float dist = sqrtf(dx * dx + dy * dy + dz * dz);
#pragma unroll
        for (int i = 0; i < 3; i++) {
            float tt = (dist - 0.75f * (float)(i + 1)) * (1.0f / 0.75f);
            float q = 1.0f - tt * tt;
            em1[i] = (q > 0.0f) ? EMBC * __expf(__fdividef(-2.0f, q)) : 0.0f;
        }
    }
    if (v0) g_emb4[e0] = make_float4(em0[0], em0[1], em0[2], 0.f);
    if (v1) g_emb4[e1] = make_float4(em1[0], em1[1], em1[2], 0.f);

    float rlo0[8], rhi0[8], rlo1[8], rhi1[8];
    compute_r_pairs2(sW1u, em0[0], em0[1], em0[2], em1[0], em1[1], em1[2],
                     rlo0, rhi0, rlo1, rhi1);

    u64 acc0[6], acc1[6];
#pragma unroll
    for (int jp = 0; jp < 6; jp++) { acc0[jp] = 0ull; acc1[jp] = 0ull; }
#pragma unroll
    for (int kp = 0; kp < 8; kp++) {
        u64 ra0 = pack2(rlo0[kp], rlo0[kp]), rb0 = pack2(rhi0[kp], rhi0[kp]);
        u64 ra1 = pack2(rlo1[kp], rlo1[kp]), rb1 = pack2(rhi1[kp], rhi1[kp]);
        const u64x2* wa = (const u64x2*)&sW2u[(2 * kp) * 6];
        const u64x2* wb = (const u64x2*)&sW2u[(2 * kp + 1) * 6];
#pragma unroll
        for (int q = 0; q < 3; q++) {
            u64x2 w = wa[q];
            fma2(acc0[2*q], ra0, w.x); fma2(acc0[2*q+1], ra0, w.y);
            fma2(acc1[2*q], ra1, w.x); fma2(acc1[2*q+1], ra1, w.y);
        }
#pragma unroll
        for (int q = 0; q < 3; q++) {
            u64x2 w = wb[q];
            fma2(acc0[2*q], rb0, w.x); fma2(acc0[2*q+1], rb0, w.y);
            fma2(acc1[2*q], rb1, w.x); fma2(acc1[2*q+1], rb1, w.y);
        }
    }

    {
        u64 fu[3] = { pack2(f0.x, f0.x), pack2(f0.y, f0.y), pack2(f0.z, f0.z) };
        u64 m01 = 0ull, m23 = 0ull;
#pragma unroll
        for (int u = 0; u < 3; u++) { fma2(m01, fu[u], acc0[u*2]); fma2(m23, fu[u], acc0[u*2+1]); }
        float m0, m1, m2, m3;
        unpack2(m01, m0, m1); unpack2(m23, m2, m3);
        if (v0) red_add_v4(&xout[d0], m0, m1, m2, m3);
    }
    {
        u64 fu[3] = { pack2(f1.x, f1.x), pack2(f1.y, f1.y), pack2(f1.z, f1.z) };
        u64 m01 = 0ull, m23 = 0ull;
#pragma unroll
        for (int u = 0; u < 3; u++) { fma2(m01, fu[u], acc1[u*2]); fma2(m23, fu[u], acc1[u*2+1]); }
        float m0, m1, m2, m3;
        unpack2(m01, m0, m1); unpack2(m23, m2, m3);
        if (v1) red_add_v4(&xout[d1], m0, m1, m2, m3);
    }
}

// ============================================================================
// core conv: 2 edges/thread; r + 16x16 GEMM + msg; zeroes zbuf for next pass
__global__ void __launch_bounds__(256, 2) core_kernel(
    const int* __restrict__ esrc, const int* __restrict__ edst,
    const float* __restrict__ w1, const float* __restrict__ w2, // w2 raw [16,48]
    const float4* __restrict__ xin, float4* __restrict__ xout,
    float4* __restrict__ zbuf, int zn, int E)
{
    __shared__ __align__(16) u64 sW1u[24];
    __shared__ __align__(16) u64 sW2u[128];  // [k*8 + jp], CCORE folded
    int t = threadIdx.x;
    if (t < 24) {
        int i = t / 8, kp = t % 8;
        sW1u[t] = pack2(w1[i * 16 + 2 * kp], w1[i * 16 + 2 * kp + 1]);
    }
    if (t < 128) {
        int k = t >> 3, jp = t & 7;
        sW2u[t] = pack2(CCORE * w2[k * 48 + 2 * jp], CCORE * w2[k * 48 + 2 * jp + 1]);
    }
    __syncthreads();

    int zi = blockIdx.x * 256 + t;
    if (zi < zn) zbuf[zi] = make_float4(0.f, 0.f, 0.f, 0.f);

    int base = blockIdx.x * 512;
    int e0 = base + t, e1 = base + 256 + t;
    bool v0 = e0 < E, v1 = e1 < E;
    int s0 = 0, d0 = 0, s1 = 0, d1 = 0;
    if (v0) { s0 = esrc[e0]; d0 = edst[e0]; }
    if (v1) { s1 = esrc[e1]; d1 = edst[e1]; }

    float4 x0 = xin[s0];
    float4 x1 = xin[s1];
    float4 em0 = g_emb4[v0 ? e0 : 0];
    float4 em1 = g_emb4[v1 ? e1 : 0];

    float rlo0[8], rhi0[8], rlo1[8], rhi1[8];
    compute_r_pairs2(sW1u, em0.x, em0.y, em0.z, em1.x, em1.y, em1.z,
                     rlo0, rhi0, rlo1, rhi1);

    u64 acc0[8], acc1[8];
#pragma unroll
    for (int jp = 0; jp < 8; jp++) { acc0[jp] = 0ull; acc1[jp] = 0ull; }
#pragma unroll
    for (int kp = 0; kp < 8; kp++) {
        u64 ra0 = pack2(rlo0[kp], rlo0[kp]), rb0 = pack2(rhi0[kp], rhi0[kp]);
        u64 ra1 = pack2(rlo1[kp], rlo1[kp]), rb1 = pack2(rhi1[kp], rhi1[kp]);
        const u64x2* wa = (const u64x2*)&sW2u[(2 * kp) * 8];
        const u64x2* wb = (const u64x2*)&sW2u[(2 * kp + 1) * 8];
#pragma unroll
        for (int q = 0; q < 4; q++) {
            u64x2 w = wa[q];
            fma2(acc0[2*q], ra0, w.x); fma2(acc0[2*q+1], ra0, w.y);
            fma2(acc1[2*q], ra1, w.x); fma2(acc1[2*q+1], ra1, w.y);
        }
#pragma unroll
        for (int q = 0; q < 4; q++) {
            u64x2 w = wb[q];
            fma2(acc0[2*q], rb0, w.x); fma2(acc0[2*q+1], rb0, w.y);
            fma2(acc1[2*q], rb1, w.x); fma2(acc1[2*q+1], rb1, w.y);
        }
    }

    {
        u64 xu[4] = { pack2(x0.x, x0.x), pack2(x0.y, x0.y), pack2(x0.z, x0.z), pack2(x0.w, x0.w) };
        u64 m01 = 0ull, m23 = 0ull;
#pragma unroll
        for (int u = 0; u < 4; u++) { fma2(m01, xu[u], acc0[u*2]); fma2(m23, xu[u], acc0[u*2+1]); }
        float m0, m1, m2, m3;
        unpack2(m01, m0, m1); unpack2(m23, m2, m3);
        if (v0) red_add_v4(&xout[d0], m0, m1, m2, m3);
    }
    {
        u64 xu[4] = { pack2(x1.x, x1.x), pack2(x1.y, x1.y), pack2(x1.z, x1.z), pack2(x1.w, x1.w) };
        u64 m01 = 0ull, m23 = 0ull;
#pragma unroll
        for (int u = 0; u < 4; u++) { fma2(m01, xu[u], acc1[u*2]); fma2(m23, xu[u], acc1[u*2+1]); }
        float m0, m1, m2, m3;
        unpack2(m01, m0, m1); unpack2(m23, m2, m3);
        if (v1) red_add_v4(&xout[d1], m0, m1, m2, m3);
    }
}

// ============================================================================
// conv3 fused with Conv1d(16,2,1): 2 edges/thread
__global__ void __launch_bounds__(256, 2) conv3_kernel(
    const int* __restrict__ esrc, const int* __restrict__ edst,
    const float* __restrict__ w1,
    const float4* __restrict__ xin, float* __restrict__ out, int E)
{
    __shared__ __align__(16) u64 sW1u[24];
    __shared__ __align__(16) u64 sMu[64];    // [k*4 + u] = (M[k,u,0], M[k,u,1])
    int t = threadIdx.x;
    if (t < 24) {
        int i = t / 8, kp = t % 8;
        sW1u[t] = pack2(w1[i * 16 + 2 * kp], w1[i * 16 + 2 * kp + 1]);
    }
    if (t < 64) {
        int k = t >> 2, u = t & 3;
        sMu[t] = pack2(g_M[k * 8 + u * 2], g_M[k * 8 + u * 2 + 1]);
    }
    __syncthreads();

    int base = blockIdx.x * 512;
    int e0 = base + t, e1 = base + 256 + t;
    bool v0 = e0 < E, v1 = e1 < E;
    int s0 = 0, d0 = 0, s1 = 0, d1 = 0;
    if (v0) { s0 = esrc[e0]; d0 = edst[e0]; }
    if (v1) { s1 = esrc[e1]; d1 = edst[e1]; }

    float4 x0 = xin[s0];
    float4 x1 = xin[s1];
    float4 em0 = g_emb4[v0 ? e0 : 0];
    float4 em1 = g_emb4[v1 ? e1 : 0];

    float rlo0[8], rhi0[8], rlo1[8], rhi1[8];
    compute_r_pairs2(sW1u, em0.x, em0.y, em0.z, em1.x, em1.y, em1.z,
                     rlo0, rhi0, rlo1, rhi1);

    u64 acc0[4], acc1[4];
#pragma unroll
    for (int u = 0; u < 4; u++) { acc0[u] = 0ull; acc1[u] = 0ull; }
#pragma unroll
    for (int kp = 0; kp < 8; kp++) {
        u64 ra0 = pack2(rlo0[kp], rlo0[kp]), rb0 = pack2(rhi0[kp], rhi0[kp]);
        u64 ra1 = pack2(rlo1[kp], rlo1[kp]), rb1 = pack2(rhi1[kp], rhi1[kp]);
        const u64x2* wa = (const u64x2*)&sMu[(2 * kp) * 4];
        const u64x2* wb = (const u64x2*)&sMu[(2 * kp + 1) * 4];
#pragma unroll
        for (int q = 0; q < 2; q++) {
            u64x2 w = wa[q];
            fma2(acc0[2*q], ra0, w.x); fma2(acc0[2*q+1], ra0, w.y);
            fma2(acc1[2*q], ra1, w.x); fma2(acc1[2*q+1], ra1, w.y);
        }
#pragma unroll
        for (int q = 0; q < 2; q++) {
            u64x2 w = wb[q];
            fma2(acc0[2*q], rb0, w.x); fma2(acc0[2*q+1], rb0, w.y);
            fma2(acc1[2*q], rb1, w.x); fma2(acc1[2*q+1], rb1, w.y);
        }
    }

    {
        u64 xu[4] = { pack2(x0.x, x0.x), pack2(x0.y, x0.y), pack2(x0.z, x0.z), pack2(x0.w, x0.w) };
        u64 mc = 0ull;
#pragma unroll
        for (int u = 0; u < 4; u++) fma2(mc, xu[u], acc0[u]);
        float m0, m1;
        unpack2(mc, m0, m1);
        if (v0) red_add_v2(out + 2 * d0, m0, m1);
    }
    {
        u64 xu[4] = { pack2(x1.x, x1.x), pack2(x1.y, x1.y), pack2(x1.z, x1.z), pack2(x1.w, x1.w) };
        u64 mc = 0ull;
#pragma unroll
        for (int u = 0; u < 4; u++) fma2(mc, xu[u], acc1[u]);
        float m0, m1;
        unpack2(mc, m0, m1);
        if (v1) red_add_v2(out + 2 * d1, m0, m1);
    }
}

// ============================================================================
extern "C" void kernel_launch(void* const* d_in, const int* in_sizes, int n_in,
                              void* d_out, int out_size)
{
    const float* pos     = (const float*)d_in[0];
    const float* feat    = (const float*)d_in[1];
    const int*   esrc    = (const int*)  d_in[2];
    const int*   edst    = (const int*)  d_in[3];
    const float* fc1_w1  = (const float*)d_in[4];
    const float* fc1_w2  = (const float*)d_in[5];
    const float* core_w1 = (const float*)d_in[6];   // [3,3,16]
    const float* core_w2 = (const float*)d_in[7];   // [3,16,48]
    const float* fc3_w1  = (const float*)d_in[8];
    const float* fc3_w2  = (const float*)d_in[9];
    const float* conv_w  = (const float*)d_in[10];
    const float* conv_b  = (const float*)d_in[11];
    float* out = (float*)d_out;

    int E = in_sizes[2];
    int n = in_sizes[0] / 3;

    float4 *xA, *xB, *xC;
    cudaGetSymbolAddress((void**)&xA, g_xA);
    cudaGetSymbolAddress((void**)&xB, g_xB);
    cudaGetSymbolAddress((void**)&xC, g_xC);

    int eb = (E + 511) / 512;   // 512 edges per 256-thread block
    int nb = (n + 255) / 256;

    mprep_kernel<<<1, 128>>>(fc3_w2, conv_w);
    prep_kernel<<<nb, 256>>>(pos, feat, conv_b, out, n);

    conv1_kernel<<<eb, 256>>>(esrc, edst, fc1_w1, fc1_w2, xA, E);
    // core1: A->B, zero C for core2's output
    core_kernel<<<eb, 256>>>(esrc, edst, core_w1 + 0,  core_w2 + 0,    xA, xB, xC, n, E);
    // core2: B->C, zero A for core3's output
    core_kernel<<<eb, 256>>>(esrc, edst, core_w1 + 48, core_w2 + 768,  xB, xC, xA, n, E);
    // core3: C->A
    core_kernel<<<eb, 256>>>(esrc, edst, core_w1 + 96, core_w2 + 1536, xC, xA, (float4*)0, 0, E);

    conv3_kernel<<<eb, 256>>>(esrc, edst, fc3_w1, xA, out, E);
}

// round 6
// speedup vs baseline: 1.6450x; 1.6450x over previous
#include <cuda_runtime.h>
#include <math.h>

#define N_NODES_MAX 100000
#define N_EDGES_MAX 1600000

typedef unsigned long long u64;
typedef ulonglong2 u64x2;

// -------- scratch (static __device__; no allocation at launch time) --------
__device__ float4 g_emb4[N_EDGES_MAX];     // (em0, em1, em2, unused)
__device__ float4 g_pos4[N_NODES_MAX];
__device__ float4 g_feat4[N_NODES_MAX];
__device__ float4 g_xA[N_NODES_MAX];
__device__ float4 g_xB[N_NODES_MAX];
__device__ float4 g_xC[N_NODES_MAX];
__device__ float  g_M[128];   // fused fc3_w2 x conv_w : [k=16][u=4][c=2], CCORE folded

// -------- constants (all e3nn normalization folded) --------
#define EMBC  (1.14136f * 7.38905609893065f * 1.7320508075688772f)
#define C1    (1.41421356237f / 48.0f)
#define CCORE (1.41421356237f / (1.7320508075688772f * 32.0f))

// -------- packed f32x2 helpers --------
__device__ __forceinline__ u64 pack2(float x, float y) {
    u64 r; asm("mov.b64 %0, {%1, %2};" : "=l"(r) : "f"(x), "f"(y)); return r;
}
__device__ __forceinline__ void unpack2(u64 v, float& x, float& y) {
    asm("mov.b64 {%0, %1}, %2;" : "=f"(x), "=f"(y) : "l"(v));
}
__device__ __forceinline__ void fma2(u64& d, u64 a, u64 b) {
    asm("fma.rn.f32x2 %0, %1, %2, %0;" : "+l"(d) : "l"(a), "l"(b));
}
__device__ __forceinline__ u64 mul2(u64 a, u64 b) {
    u64 d; asm("mul.rn.f32x2 %0, %1, %2;" : "=l"(d) : "l"(a), "l"(b)); return d;
}

// -------- vectorized global reductions (sm_90+) --------
__device__ __forceinline__ void red_add_v4(float4* addr, float a, float b, float c, float d) {
    asm volatile("red.global.add.v4.f32 [%0], {%1, %2, %3, %4};"
                 :: "l"(addr), "f"(a), "f"(b), "f"(c), "f"(d) : "memory");
}
__device__ __forceinline__ void red_add_v2(float* addr, float a, float b) {
    asm volatile("red.global.add.v2.f32 [%0], {%1, %2};"
                 :: "l"(addr), "f"(a), "f"(b) : "memory");
}

// ============================================================================
// prep: pack pos/feat into float4 tables, zero xA/xB, write bias into out
__global__ void __launch_bounds__(256) prep_kernel(
    const float* __restrict__ pos, const float* __restrict__ feat,
    const float* __restrict__ conv_b, float* __restrict__ out, int n)
{
    int i = blockIdx.x * 256 + threadIdx.x;
    if (i >= n) return;
    g_pos4[i]  = make_float4(pos[3 * i], pos[3 * i + 1], pos[3 * i + 2], 0.f);
    g_feat4[i] = make_float4(feat[3 * i], feat[3 * i + 1], feat[3 * i + 2], 0.f);
    g_xA[i] = make_float4(0.f, 0.f, 0.f, 0.f);
    g_xB[i] = make_float4(0.f, 0.f, 0.f, 0.f);
    ((float2*)out)[i] = make_float2(conv_b[0], conv_b[1]);
}

// M[k,u,c] = CCORE * sum_w fc3_w2[k, u*16+w] * conv_w[c, w]
__global__ void mprep_kernel(const float* __restrict__ fc3_w2, const float* __restrict__ conv_w) {
    int t = threadIdx.x;            // 128
    int k = t >> 3, u = (t >> 1) & 3, c = t & 1;
    float s = 0.f;
#pragma unroll
    for (int w = 0; w < 16; w++)
        s += fc3_w2[k * 64 + u * 16 + w] * conv_w[c * 16 + w];
    g_M[t] = CCORE * s;
}

// -------- packed r[16] (one edge): 12 LDS.128 + 24 FFMA2 + 16 MAX ----------
__device__ __forceinline__ void compute_r_pairs(const u64* sW1u, float e0, float e1, float e2,
                                                float* rlo, float* rhi) {
    u64 e02 = pack2(e0, e0), e12 = pack2(e1, e1), e22 = pack2(e2, e2);
    const u64x2* w0 = (const u64x2*)(sW1u);
    const u64x2* w1 = (const u64x2*)(sW1u + 8);
    const u64x2* w2 = (const u64x2*)(sW1u + 16);
#pragma unroll
    for (int q = 0; q < 4; q++) {
        u64x2 a = w0[q], b = w1[q], c = w2[q];
        u64 v0 = mul2(e02, a.x);
        u64 v1 = mul2(e02, a.y);
        fma2(v0, e12, b.x); fma2(v1, e12, b.y);
        fma2(v0, e22, c.x); fma2(v1, e22, c.y);
        float p, r; unpack2(v0, p, r);
        rlo[2 * q] = fmaxf(p, 0.f); rhi[2 * q] = fmaxf(r, 0.f);
        unpack2(v1, p, r);
        rlo[2 * q + 1] = fmaxf(p, 0.f); rhi[2 * q + 1] = fmaxf(r, 0.f);
    }
}

// ============================================================================
// conv1: 1 edge/thread (R4-proven); emb precompute + r + 16x12 GEMM + scatter
__global__ void __launch_bounds__(256) conv1_kernel(
    const int* __restrict__ esrc, const int* __restrict__ edst,
    const float* __restrict__ w1, const float* __restrict__ w2,
    float4* __restrict__ xout, int E)
{
    __shared__ __align__(16) u64 sW1u[24];
    __shared__ __align__(16) u64 sW2u[96];   // [k*6 + jp], C1 folded
    int t = threadIdx.x;
    if (t < 24) {
        int i = t / 8, kp = t % 8;
        sW1u[t] = pack2(w1[i * 16 + 2 * kp], w1[i * 16 + 2 * kp + 1]);
    }
    if (t < 96) {
        int k = t / 6, jp = t % 6;
        sW2u[t] = pack2(C1 * w2[k * 12 + 2 * jp], C1 * w2[k * 12 + 2 * jp + 1]);
    }
    __syncthreads();

    int e = blockIdx.x * 256 + t;
    if (e >= E) return;
    int s = esrc[e], d = edst[e];

    float4 ps = g_pos4[s];
    float4 pd = g_pos4[d];
    float4 f  = g_feat4[s];

    float dx = pd.x - ps.x, dy = pd.y - ps.y, dz = pd.z - ps.z;
    float dist = sqrtf(dx * dx + dy * dy + dz * dz);

    float em[3];
#pragma unroll
    for (int i = 0; i < 3; i++) {
        float tt = (dist - 0.75f * (float)(i + 1)) * (1.0f / 0.75f);
        float q = 1.0f - tt * tt;
        em[i] = (q > 0.0f) ? EMBC * __expf(__fdividef(-2.0f, q)) : 0.0f;
    }
    g_emb4[e] = make_float4(em[0], em[1], em[2], 0.f);

    float rlo[8], rhi[8];
    compute_r_pairs(sW1u, em[0], em[1], em[2], rlo, rhi);

    u64 acc[6];
#pragma unroll
    for (int jp = 0; jp < 6; jp++) acc[jp] = 0ull;
#pragma unroll
    for (int kp = 0; kp < 8; kp++) {
        u64 ra = pack2(rlo[kp], rlo[kp]);
        u64 rb = pack2(rhi[kp], rhi[kp]);
        const u64x2* wa = (const u64x2*)&sW2u[(2 * kp) * 6];
        const u64x2* wb = (const u64x2*)&sW2u[(2 * kp + 1) * 6];
#pragma unroll
        for (int q = 0; q < 3; q++) {
            u64x2 w = wa[q];
            fma2(acc[2 * q], ra, w.x); fma2(acc[2 * q + 1], ra, w.y);
        }
#pragma unroll
        for (int q = 0; q < 3; q++) {
            u64x2 w = wb[q];
            fma2(acc[2 * q], rb, w.x); fma2(acc[2 * q + 1], rb, w.y);
        }
    }

    u64 fu[3] = { pack2(f.x, f.x), pack2(f.y, f.y), pack2(f.z, f.z) };
    u64 m01 = 0ull, m23 = 0ull;
#pragma unroll
    for (int u = 0; u < 3; u++) { fma2(m01, fu[u], acc[u * 2]); fma2(m23, fu[u], acc[u * 2 + 1]); }
    float m0, m1, m2, m3;
    unpack2(m01, m0, m1); unpack2(m23, m2, m3);
    red_add_v4(&xout[d], m0, m1, m2, m3);
}

// ============================================================================
// core conv: 2 edges/thread, kp-INTERLEAVED r (no r arrays -> low regs);
// weights LDS shared across both edges; zeroes zbuf for next pass
__global__ void __launch_bounds__(256, 3) core_kernel(
    const int* __restrict__ esrc, const int* __restrict__ edst,
    const float* __restrict__ w1, const float* __restrict__ w2, // w2 raw [16,48]
    const float4* __restrict__ xin, float4* __restrict__ xout,
    float4* __restrict__ zbuf, int zn, int E)
{
    __shared__ __align__(16) u64 sW1u[24];   // [i*8 + kp]
    __shared__ __align__(16) u64 sW2u[128];  // [k*8 + jp], CCORE folded
    int t = threadIdx.x;
    if (t < 24) {
        int i = t / 8, kp = t % 8;
        sW1u[t] = pack2(w1[i * 16 + 2 * kp], w1[i * 16 + 2 * kp + 1]);
    }
    if (t < 128) {
        int k = t >> 3, jp = t & 7;
        sW2u[t] = pack2(CCORE * w2[k * 48 + 2 * jp], CCORE * w2[k * 48 + 2 * jp + 1]);
    }
    __syncthreads();

    int zi = blockIdx.x * 256 + t;
    if (zi < zn) zbuf[zi] = make_float4(0.f, 0.f, 0.f, 0.f);

    int base = blockIdx.x * 512;
    int e0 = base + t, e1 = base + 256 + t;
    bool v0 = e0 < E, v1 = e1 < E;
    int s0 = 0, d0 = 0, s1 = 0, d1 = 0;
    if (v0) { s0 = esrc[e0]; d0 = edst[e0]; }
    if (v1) { s1 = esrc[e1]; d1 = edst[e1]; }

    float4 x0 = xin[s0];
    float4 x1 = xin[s1];
    float4 emA = g_emb4[v0 ? e0 : 0];
    float4 emB = g_emb4[v1 ? e1 : 0];

    u64 eA0 = pack2(emA.x, emA.x), eA1 = pack2(emA.y, emA.y), eA2 = pack2(emA.z, emA.z);
    u64 eB0 = pack2(emB.x, emB.x), eB1 = pack2(emB.y, emB.y), eB2 = pack2(emB.z, emB.z);

    u64 acc0[8], acc1[8];
#pragma unroll
    for (int jp = 0; jp < 8; jp++) { acc0[jp] = 0ull; acc1[jp] = 0ull; }

#pragma unroll
    for (int kp = 0; kp < 8; kp++) {
        // r pair (k=2kp, 2kp+1) for both edges, computed on the fly
        u64 wi0 = sW1u[kp], wi1 = sW1u[8 + kp], wi2 = sW1u[16 + kp];
        u64 vA = mul2(eA0, wi0); fma2(vA, eA1, wi1); fma2(vA, eA2, wi2);
        u64 vB = mul2(eB0, wi0); fma2(vB, eB1, wi1); fma2(vB, eB2, wi2);
        float a0, a1, b0, b1;
        unpack2(vA, a0, a1); unpack2(vB, b0, b1);
        a0 = fmaxf(a0, 0.f); a1 = fmaxf(a1, 0.f);
        b0 = fmaxf(b0, 0.f); b1 = fmaxf(b1, 0.f);
        u64 raA = pack2(a0, a0), rbA = pack2(a1, a1);
        u64 raB = pack2(b0, b0), rbB = pack2(b1, b1);

        const u64x2* wa = (const u64x2*)&sW2u[(2 * kp) * 8];
        const u64x2* wb = (const u64x2*)&sW2u[(2 * kp + 1) * 8];
#pragma unroll
        for (int q = 0; q < 4; q++) {
            u64x2 w = wa[q];
            fma2(acc0[2*q], raA, w.x); fma2(acc0[2*q+1], raA, w.y);
            fma2(acc1[2*q], raB, w.x); fma2(acc1[2*q+1], raB, w.y);
        }
#pragma unroll
        for (int q = 0; q < 4; q++) {
            u64x2 w = wb[q];
            fma2(acc0[2*q], rbA, w.x); fma2(acc0[2*q+1], rbA, w.y);
            fma2(acc1[2*q], rbB, w.x); fma2(acc1[2*q+1], rbB, w.y);
        }
    }

    {
        u64 xu[4] = { pack2(x0.x, x0.x), pack2(x0.y, x0.y), pack2(x0.z, x0.z), pack2(x0.w, x0.w) };
        u64 m01 = 0ull, m23 = 0ull;
#pragma unroll
        for (int u = 0; u < 4; u++) { fma2(m01, xu[u], acc0[u*2]); fma2(m23, xu[u], acc0[u*2+1]); }
        float m0, m1, m2, m3;
        unpack2(m01, m0, m1); unpack2(m23, m2, m3);
        if (v0) red_add_v4(&xout[d0], m0, m1, m2, m3);
    }
    {
        u64 xu[4] = { pack2(x1.x, x1.x), pack2(x1.y, x1.y), pack2(x1.z, x1.z), pack2(x1.w, x1.w) };
        u64 m01 = 0ull, m23 = 0ull;
#pragma unroll
        for (int u = 0; u < 4; u++) { fma2(m01, xu[u], acc1[u*2]); fma2(m23, xu[u], acc1[u*2+1]); }
        float m0, m1, m2, m3;
        unpack2(m01, m0, m1); unpack2(m23, m2, m3);
        if (v1) red_add_v4(&xout[d1], m0, m1, m2, m3);
    }
}

// ============================================================================
// conv3 fused with Conv1d(16,2,1): 2 edges/thread, kp-interleaved r
__global__ void __launch_bounds__(256, 3) conv3_kernel(
    const int* __restrict__ esrc, const int* __restrict__ edst,
    const float* __restrict__ w1,
    const float4* __restrict__ xin, float* __restrict__ out, int E)
{
    __shared__ __align__(16) u64 sW1u[24];
    __shared__ __align__(16) u64 sMu[64];    // [k*4 + u] = (M[k,u,0], M[k,u,1])
    int t = threadIdx.x;
    if (t < 24) {
        int i = t / 8, kp = t % 8;
        sW1u[t] = pack2(w1[i * 16 + 2 * kp], w1[i * 16 + 2 * kp + 1]);
    }
    if (t < 64) {
        int k = t >> 2, u = t & 3;
        sMu[t] = pack2(g_M[k * 8 + u * 2], g_M[k * 8 + u * 2 + 1]);
    }
    __syncthreads();

    int base = blockIdx.x * 512;
    int e0 = base + t, e1 = base + 256 + t;
    bool v0 = e0 < E, v1 = e1 < E;
    int s0 = 0, d0 = 0, s1 = 0, d1 = 0;
    if (v0) { s0 = esrc[e0]; d0 = edst[e0]; }
    if (v1) { s1 = esrc[e1]; d1 = edst[e1]; }

    float4 x0 = xin[s0];
    float4 x1 = xin[s1];
    float4 emA = g_emb4[v0 ? e0 : 0];
    float4 emB = g_emb4[v1 ? e1 : 0];

    u64 eA0 = pack2(emA.x, emA.x), eA1 = pack2(emA.y, emA.y), eA2 = pack2(emA.z, emA.z);
    u64 eB0 = pack2(emB.x, emB.x), eB1 = pack2(emB.y, emB.y), eB2 = pack2(emB.z, emB.z);

    u64 acc0[4], acc1[4];
#pragma unroll
    for (int u = 0; u < 4; u++) { acc0[u] = 0ull; acc1[u] = 0ull; }

#pragma unroll
    for (int kp = 0; kp < 8; kp++) {
        u64 wi0 = sW1u[kp], wi1 = sW1u[8 + kp], wi2 = sW1u[16 + kp];
        u64 vA = mul2(eA0, wi0); fma2(vA, eA1, wi1); fma2(vA, eA2, wi2);
        u64 vB = mul2(eB0, wi0); fma2(vB, eB1, wi1); fma2(vB, eB2, wi2);
        float a0, a1, b0, b1;
        unpack2(vA, a0, a1); unpack2(vB, b0, b1);
        a0 = fmaxf(a0, 0.f); a1 = fmaxf(a1, 0.f);
        b0 = fmaxf(b0, 0.f); b1 = fmaxf(b1, 0.f);
        u64 raA = pack2(a0, a0), rbA = pack2(a1, a1);
        u64 raB = pack2(b0, b0), rbB = pack2(b1, b1);

        const u64x2* wa = (const u64x2*)&sMu[(2 * kp) * 4];
        const u64x2* wb = (const u64x2*)&sMu[(2 * kp + 1) * 4];
#pragma unroll
        for (int q = 0; q < 2; q++) {
            u64x2 w = wa[q];
            fma2(acc0[2*q], raA, w.x); fma2(acc0[2*q+1], raA, w.y);
            fma2(acc1[2*q], raB, w.x); fma2(acc1[2*q+1], raB, w.y);
        }
#pragma unroll
        for (int q = 0; q < 2; q++) {
            u64x2 w = wb[q];
            fma2(acc0[2*q], rbA, w.x); fma2(acc0[2*q+1], rbA, w.y);
            fma2(acc1[2*q], rbB, w.x); fma2(acc1[2*q+1], rbB, w.y);
        }
    }

    {
        u64 xu[4] = { pack2(x0.x, x0.x), pack2(x0.y, x0.y), pack2(x0.z, x0.z), pack2(x0.w, x0.w) };
        u64 mc = 0ull;
#pragma unroll
        for (int u = 0; u < 4; u++) fma2(mc, xu[u], acc0[u]);
        float m0, m1;
        unpack2(mc, m0, m1);
        if (v0) red_add_v2(out + 2 * d0, m0, m1);
    }
    {
        u64 xu[4] = { pack2(x1.x, x1.x), pack2(x1.y, x1.y), pack2(x1.z, x1.z), pack2(x1.w, x1.w) };
        u64 mc = 0ull;
#pragma unroll
        for (int u = 0; u < 4; u++) fma2(mc, xu[u], acc1[u]);
        float m0, m1;
        unpack2(mc, m0, m1);
        if (v1) red_add_v2(out + 2 * d1, m0, m1);
    }
}

// ============================================================================
extern "C" void kernel_launch(void* const* d_in, const int* in_sizes, int n_in,
                              void* d_out, int out_size)
{
    const float* pos     = (const float*)d_in[0];
    const float* feat    = (const float*)d_in[1];
    const int*   esrc    = (const int*)  d_in[2];
    const int*   edst    = (const int*)  d_in[3];
    const float* fc1_w1  = (const float*)d_in[4];
    const float* fc1_w2  = (const float*)d_in[5];
    const float* core_w1 = (const float*)d_in[6];   // [3,3,16]
    const float* core_w2 = (const float*)d_in[7];   // [3,16,48]
    const float* fc3_w1  = (const float*)d_in[8];
    const float* fc3_w2  = (const float*)d_in[9];
    const float* conv_w  = (const float*)d_in[10];
    const float* conv_b  = (const float*)d_in[11];
    float* out = (float*)d_out;

    int E = in_sizes[2];
    int n = in_sizes[0] / 3;

    float4 *xA, *xB, *xC;
    cudaGetSymbolAddress((void**)&xA, g_xA);
    cudaGetSymbolAddress((void**)&xB, g_xB);
    cudaGetSymbolAddress((void**)&xC, g_xC);

    int eb1 = (E + 255) / 256;   // 1 edge/thread kernels
    int eb2 = (E + 511) / 512;   // 2 edges/thread kernels
    int nb  = (n + 255) / 256;

    mprep_kernel<<<1, 128>>>(fc3_w2, conv_w);
    prep_kernel<<<nb, 256>>>(pos, feat, conv_b, out, n);

    conv1_kernel<<<eb1, 256>>>(esrc, edst, fc1_w1, fc1_w2, xA, E);
    // core1: A->B, zero C for core2's output
    core_kernel<<<eb2, 256>>>(esrc, edst, core_w1 + 0,  core_w2 + 0,    xA, xB, xC, n, E);
    // core2: B->C, zero A for core3's output
    core_kernel<<<eb2, 256>>>(esrc, edst, core_w1 + 48, core_w2 + 768,  xB, xC, xA, n, E);
    // core3: C->A
    core_kernel<<<eb2, 256>>>(esrc, edst, core_w1 + 96, core_w2 + 1536, xC, xA, (float4*)0, 0, E);

    conv3_kernel<<<eb2, 256>>>(esrc, edst, fc3_w1, xA, out, E);
}

// round 7
// speedup vs baseline: 1.7988x; 1.0935x over previous
#include <cuda_runtime.h>
#include <math.h>

#define N_NODES_MAX 100000
#define N_EDGES_MAX 1600000

typedef unsigned long long u64;
typedef ulonglong2 u64x2;

// -------- scratch (static __device__; no allocation at launch time) --------
__device__ float4 g_emb4[N_EDGES_MAX];     // (em0, em1, em2, unused)
__device__ float4 g_pos4[N_NODES_MAX];
__device__ float4 g_feat4[N_NODES_MAX];
__device__ float4 g_xA[N_NODES_MAX];
__device__ float4 g_xB[N_NODES_MAX];
__device__ float4 g_xC[N_NODES_MAX];
__device__ float  g_M[128];   // fused fc3_w2 x conv_w : [k=16][u=4][c=2], CCORE folded

// -------- constants (all e3nn normalization folded) --------
#define EMBC  (1.14136f * 7.38905609893065f * 1.7320508075688772f)
#define C1    (1.41421356237f / 48.0f)
#define CCORE (1.41421356237f / (1.7320508075688772f * 32.0f))

// -------- packed f32x2 helpers --------
__device__ __forceinline__ u64 pack2(float x, float y) {
    u64 r; asm("mov.b64 %0, {%1, %2};" : "=l"(r) : "f"(x), "f"(y)); return r;
}
__device__ __forceinline__ void unpack2(u64 v, float& x, float& y) {
    asm("mov.b64 {%0, %1}, %2;" : "=f"(x), "=f"(y) : "l"(v));
}
__device__ __forceinline__ void fma2(u64& d, u64 a, u64 b) {
    asm("fma.rn.f32x2 %0, %1, %2, %0;" : "+l"(d) : "l"(a), "l"(b));
}
__device__ __forceinline__ u64 mul2(u64 a, u64 b) {
    u64 d; asm("mul.rn.f32x2 %0, %1, %2;" : "=l"(d) : "l"(a), "l"(b)); return d;
}

// -------- vectorized global reductions (sm_90+) --------
__device__ __forceinline__ void red_add_v4(float4* addr, float a, float b, float c, float d) {
    asm volatile("red.global.add.v4.f32 [%0], {%1, %2, %3, %4};"
                 :: "l"(addr), "f"(a), "f"(b), "f"(c), "f"(d) : "memory");
}
__device__ __forceinline__ void red_add_v2(float* addr, float a, float b) {
    asm volatile("red.global.add.v2.f32 [%0], {%1, %2};"
                 :: "l"(addr), "f"(a), "f"(b) : "memory");
}

// ============================================================================
// prep: pack pos/feat into float4 tables, zero xA/xB, write bias into out
__global__ void __launch_bounds__(256) prep_kernel(
    const float* __restrict__ pos, const float* __restrict__ feat,
    const float* __restrict__ conv_b, float* __restrict__ out, int n)
{
    int i = blockIdx.x * 256 + threadIdx.x;
    if (i >= n) return;
    g_pos4[i]  = make_float4(pos[3 * i], pos[3 * i + 1], pos[3 * i + 2], 0.f);
    g_feat4[i] = make_float4(feat[3 * i], feat[3 * i + 1], feat[3 * i + 2], 0.f);
    g_xA[i] = make_float4(0.f, 0.f, 0.f, 0.f);
    g_xB[i] = make_float4(0.f, 0.f, 0.f, 0.f);
    ((float2*)out)[i] = make_float2(conv_b[0], conv_b[1]);
}

// M[k,u,c] = CCORE * sum_w fc3_w2[k, u*16+w] * conv_w[c, w]
__global__ void mprep_kernel(const float* __restrict__ fc3_w2, const float* __restrict__ conv_w) {
    int t = threadIdx.x;            // 128
    int k = t >> 3, u = (t >> 1) & 3, c = t & 1;
    float s = 0.f;
#pragma unroll
    for (int w = 0; w < 16; w++)
        s += fc3_w2[k * 64 + u * 16 + w] * conv_w[c * 16 + w];
    g_M[t] = CCORE * s;
}

// r pair for two edges at slice kp: 3 uniform LDS.64 + 6 FFMA2 + relu
#define R_PAIRS(kp)                                                             \
    u64 wi0 = sW1u[kp], wi1 = sW1u[8 + kp], wi2 = sW1u[16 + kp];                \
    u64 vA = mul2(eA0, wi0); fma2(vA, eA1, wi1); fma2(vA, eA2, wi2);            \
    u64 vB = mul2(eB0, wi0); fma2(vB, eB1, wi1); fma2(vB, eB2, wi2);            \
    float a0, a1, b0, b1;                                                       \
    unpack2(vA, a0, a1); unpack2(vB, b0, b1);                                   \
    a0 = fmaxf(a0, 0.f); a1 = fmaxf(a1, 0.f);                                   \
    b0 = fmaxf(b0, 0.f); b1 = fmaxf(b1, 0.f);                                   \
    u64 raA = pack2(a0, a0), rbA = pack2(a1, a1);                               \
    u64 raB = pack2(b0, b0), rbB = pack2(b1, b1);

// ============================================================================
// conv1: 2 edges/thread, t-form; emb precompute + scatter
__global__ void __launch_bounds__(128, 7) conv1_kernel(
    const int* __restrict__ esrc, const int* __restrict__ edst,
    const float* __restrict__ w1, const float* __restrict__ w2,
    float4* __restrict__ xout, int E)
{
    __shared__ __align__(16) u64 sW1u[24];
    __shared__ __align__(16) u64 sW2u[96];   // [k*6 + jp], C1 folded
    int t = threadIdx.x;
    if (t < 24) {
        int i = t / 8, kp = t % 8;
        sW1u[t] = pack2(w1[i * 16 + 2 * kp], w1[i * 16 + 2 * kp + 1]);
    }
    if (t < 96) {
        int k = t / 6, jp = t % 6;
        sW2u[t] = pack2(C1 * w2[k * 12 + 2 * jp], C1 * w2[k * 12 + 2 * jp + 1]);
    }
    __syncthreads();

    int base = blockIdx.x * 256;
    int e0 = base + t, e1 = base + 128 + t;
    bool v0 = e0 < E, v1 = e1 < E;
    int s0 = 0, d0 = 0, s1 = 0, d1 = 0;
    if (v0) { s0 = esrc[e0]; d0 = edst[e0]; }
    if (v1) { s1 = esrc[e1]; d1 = edst[e1]; }

    float4 ps0 = g_pos4[s0], pd0 = g_pos4[d0], f0 = g_feat4[s0];
    float4 ps1 = g_pos4[s1], pd1 = g_pos4[d1], f1 = g_feat4[s1];

    float emA[3], emB[3];
    {
        float dx = pd0.x - ps0.x, dy = pd0.y - ps0.y, dz = pd0.z - ps0.z;
        float dist = sqrtf(dx * dx + dy * dy + dz * dz);
#pragma unroll
        for (int i = 0; i < 3; i++) {
            float tt = (dist - 0.75f * (float)(i + 1)) * (1.0f / 0.75f);
            float q = 1.0f - tt * tt;
            emA[i] = (q > 0.0f) ? EMBC * __expf(__fdividef(-2.0f, q)) : 0.0f;
        }
    }
    {
        float dx = pd1.x - ps1.x, dy = pd1.y - ps1.y, dz = pd1.z - ps1.z;
        float dist = sqrtf(dx * dx + dy * dy + dz * dz);
#pragma unroll
        for (int i = 0; i < 3; i++) {
            float tt = (dist - 0.75f * (float)(i + 1)) * (1.0f / 0.75f);
            float q = 1.0f - tt * tt;
            emB[i] = (q > 0.0f) ? EMBC * __expf(__fdividef(-2.0f, q)) : 0.0f;
        }
    }
    if (v0) g_emb4[e0] = make_float4(emA[0], emA[1], emA[2], 0.f);
    if (v1) g_emb4[e1] = make_float4(emB[0], emB[1], emB[2], 0.f);

    u64 eA0 = pack2(emA[0], emA[0]), eA1 = pack2(emA[1], emA[1]), eA2 = pack2(emA[2], emA[2]);
    u64 eB0 = pack2(emB[0], emB[0]), eB1 = pack2(emB[1], emB[1]), eB2 = pack2(emB[2], emB[2]);
    u64 xA[3] = { pack2(f0.x, f0.x), pack2(f0.y, f0.y), pack2(f0.z, f0.z) };
    u64 xB[3] = { pack2(f1.x, f1.x), pack2(f1.y, f1.y), pack2(f1.z, f1.z) };

    u64 mA01 = 0ull, mA23 = 0ull, mB01 = 0ull, mB23 = 0ull;
#pragma unroll
    for (int kp = 0; kp < 8; kp++) {
        R_PAIRS(kp)
        {   // k = 2kp
            const u64x2* wr = (const u64x2*)&sW2u[(2 * kp) * 6];
            u64 tA01, tA23, tB01, tB23;
#pragma unroll
            for (int u = 0; u < 3; u++) {
                u64x2 w = wr[u];
                if (u == 0) {
                    tA01 = mul2(xA[0], w.x); tA23 = mul2(xA[0], w.y);
                    tB01 = mul2(xB[0], w.x); tB23 = mul2(xB[0], w.y);
                } else {
                    fma2(tA01, xA[u], w.x); fma2(tA23, xA[u], w.y);
                    fma2(tB01, xB[u], w.x); fma2(tB23, xB[u], w.y);
                }
            }
            fma2(mA01, raA, tA01); fma2(mA23, raA, tA23);
            fma2(mB01, raB, tB01); fma2(mB23, raB, tB23);
        }
        {   // k = 2kp+1
            const u64x2* wr = (const u64x2*)&sW2u[(2 * kp + 1) * 6];
            u64 tA01, tA23, tB01, tB23;
#pragma unroll
            for (int u = 0; u < 3; u++) {
                u64x2 w = wr[u];
                if (u == 0) {
                    tA01 = mul2(xA[0], w.x); tA23 = mul2(xA[0], w.y);
                    tB01 = mul2(xB[0], w.x); tB23 = mul2(xB[0], w.y);
                } else {
                    fma2(tA01, xA[u], w.x); fma2(tA23, xA[u], w.y);
                    fma2(tB01, xB[u], w.x); fma2(tB23, xB[u], w.y);
                }
            }
            fma2(mA01, rbA, tA01); fma2(mA23, rbA, tA23);
            fma2(mB01, rbB, tB01); fma2(mB23, rbB, tB23);
        }
    }

    float m0, m1, m2, m3;
    unpack2(mA01, m0, m1); unpack2(mA23, m2, m3);
    if (v0) red_add_v4(&xout[d0], m0, m1, m2, m3);
    unpack2(mB01, m0, m1); unpack2(mB23, m2, m3);
    if (v1) red_add_v4(&xout[d1], m0, m1, m2, m3);
}

// ============================================================================
// core conv: 2 edges/thread, t-form low-register; zeroes zbuf for next pass
__global__ void __launch_bounds__(128, 7) core_kernel(
    const int* __restrict__ esrc, const int* __restrict__ edst,
    const float* __restrict__ w1, const float* __restrict__ w2, // w2 raw [16,48]
    const float4* __restrict__ xin, float4* __restrict__ xout,
    float4* __restrict__ zbuf, int zn, int E)
{
    __shared__ __align__(16) u64 sW1u[24];   // [i*8 + kp]
    __shared__ __align__(16) u64 sW2u[128];  // [k*8 + jp], CCORE folded; jp = u*2 + wpair
    int t = threadIdx.x;
    if (t < 24) {
        int i = t / 8, kp = t % 8;
        sW1u[t] = pack2(w1[i * 16 + 2 * kp], w1[i * 16 + 2 * kp + 1]);
    }
    {
        int k = t >> 3, jp = t & 7;
        sW2u[t] = pack2(CCORE * w2[k * 48 + 2 * jp], CCORE * w2[k * 48 + 2 * jp + 1]);
    }
    __syncthreads();

    int zi = blockIdx.x * 128 + t;
    if (zi < zn) zbuf[zi] = make_float4(0.f, 0.f, 0.f, 0.f);

    int base = blockIdx.x * 256;
    int e0 = base + t, e1 = base + 128 + t;
    bool v0 = e0 < E, v1 = e1 < E;
    int s0 = 0, d0 = 0, s1 = 0, d1 = 0;
    if (v0) { s0 = esrc[e0]; d0 = edst[e0]; }
    if (v1) { s1 = esrc[e1]; d1 = edst[e1]; }

    float4 x0 = xin[s0];
    float4 x1 = xin[s1];
    float4 emA = g_emb4[v0 ? e0 : 0];
    float4 emB = g_emb4[v1 ? e1 : 0];

    u64 eA0 = pack2(emA.x, emA.x), eA1 = pack2(emA.y, emA.y), eA2 = pack2(emA.z, emA.z);
    u64 eB0 = pack2(emB.x, emB.x), eB1 = pack2(emB.y, emB.y), eB2 = pack2(emB.z, emB.z);
    u64 xA[4] = { pack2(x0.x, x0.x), pack2(x0.y, x0.y), pack2(x0.z, x0.z), pack2(x0.w, x0.w) };
    u64 xB[4] = { pack2(x1.x, x1.x), pack2(x1.y, x1.y), pack2(x1.z, x1.z), pack2(x1.w, x1.w) };

    u64 mA01 = 0ull, mA23 = 0ull, mB01 = 0ull, mB23 = 0ull;
#pragma unroll
    for (int kp = 0; kp < 8; kp++) {
        R_PAIRS(kp)
        {   // k = 2kp
            const u64x2* wr = (const u64x2*)&sW2u[(2 * kp) * 8];
            u64 tA01, tA23, tB01, tB23;
#pragma unroll
            for (int u = 0; u < 4; u++) {
                u64x2 w = wr[u];
                if (u == 0) {
                    tA01 = mul2(xA[0], w.x); tA23 = mul2(xA[0], w.y);
                    tB01 = mul2(xB[0], w.x); tB23 = mul2(xB[0], w.y);
                } else {
                    fma2(tA01, xA[u], w.x); fma2(tA23, xA[u], w.y);
                    fma2(tB01, xB[u], w.x); fma2(tB23, xB[u], w.y);
                }
            }
            fma2(mA01, raA, tA01); fma2(mA23, raA, tA23);
            fma2(mB01, raB, tB01); fma2(mB23, raB, tB23);
        }
        {   // k = 2kp+1
            const u64x2* wr = (const u64x2*)&sW2u[(2 * kp + 1) * 8];
            u64 tA01, tA23, tB01, tB23;
#pragma unroll
            for (int u = 0; u < 4; u++) {
                u64x2 w = wr[u];
                if (u == 0) {
                    tA01 = mul2(xA[0], w.x); tA23 = mul2(xA[0], w.y);
                    tB01 = mul2(xB[0], w.x); tB23 = mul2(xB[0], w.y);
                } else {
                    fma2(tA01, xA[u], w.x); fma2(tA23, xA[u], w.y);
                    fma2(tB01, xB[u], w.x); fma2(tB23, xB[u], w.y);
                }
            }
            fma2(mA01, rbA, tA01); fma2(mA23, rbA, tA23);
            fma2(mB01, rbB, tB01); fma2(mB23, rbB, tB23);
        }
    }

    float m0, m1, m2, m3;
    unpack2(mA01, m0, m1); unpack2(mA23, m2, m3);
    if (v0) red_add_v4(&xout[d0], m0, m1, m2, m3);
    unpack2(mB01, m0, m1); unpack2(mB23, m2, m3);
    if (v1) red_add_v4(&xout[d1], m0, m1, m2, m3);
}

// ============================================================================
// conv3 fused with Conv1d(16,2,1): 2 edges/thread, t-form
__global__ void __launch_bounds__(128, 7) conv3_kernel(
    const int* __restrict__ esrc, const int* __restrict__ edst,
    const float* __restrict__ w1,
    const float4* __restrict__ xin, float* __restrict__ out, int E)
{
    __shared__ __align__(16) u64 sW1u[24];
    __shared__ __align__(16) u64 sMu[64];    // [k*4 + u] = (M[k,u,0], M[k,u,1])
    int t = threadIdx.x;
    if (t < 24) {
        int i = t / 8, kp = t % 8;
        sW1u[t] = pack2(w1[i * 16 + 2 * kp], w1[i * 16 + 2 * kp + 1]);
    }
    if (t < 64) {
        int k = t >> 2, u = t & 3;
        sMu[t] = pack2(g_M[k * 8 + u * 2], g_M[k * 8 + u * 2 + 1]);
    }
    __syncthreads();

    int base = blockIdx.x * 256;
    int e0 = base + t, e1 = base + 128 + t;
    bool v0 = e0 < E, v1 = e1 < E;
    int s0 = 0, d0 = 0, s1 = 0, d1 = 0;
    if (v0) { s0 = esrc[e0]; d0 = edst[e0]; }
    if (v1) { s1 = esrc[e1]; d1 = edst[e1]; }

    float4 x0 = xin[s0];
    float4 x1 = xin[s1];
    float4 emA = g_emb4[v0 ? e0 : 0];
    float4 emB = g_emb4[v1 ? e1 : 0];

    u64 eA0 = pack2(emA.x, emA.x), eA1 = pack2(emA.y, emA.y), eA2 = pack2(emA.z, emA.z);
    u64 eB0 = pack2(emB.x, emB.x), eB1 = pack2(emB.y, emB.y), eB2 = pack2(emB.z, emB.z);
    u64 xA[4] = { pack2(x0.x, x0.x), pack2(x0.y, x0.y), pack2(x0.z, x0.z), pack2(x0.w, x0.w) };
    u64 xB[4] = { pack2(x1.x, x1.x), pack2(x1.y, x1.y), pack2(x1.z, x1.z), pack2(x1.w, x1.w) };

    u64 mA = 0ull, mB = 0ull;   // (c0, c1) per edge
#pragma unroll
    for (int kp = 0; kp < 8; kp++) {
        R_PAIRS(kp)
        {   // k = 2kp
            const u64x2* wr = (const u64x2*)&sMu[(2 * kp) * 4];
            u64x2 wlo = wr[0], whi = wr[1];
            u64 tA = mul2(xA[0], wlo.x); fma2(tA, xA[1], wlo.y);
            fma2(tA, xA[2], whi.x); fma2(tA, xA[3], whi.y);
            u64 tB = mul2(xB[0], wlo.x); fma2(tB, xB[1], wlo.y);
            fma2(tB, xB[2], whi.x); fma2(tB, xB[3], whi.y);
            fma2(mA, raA, tA); fma2(mB, raB, tB);
        }
        {   // k = 2kp+1
            const u64x2* wr = (const u64x2*)&sMu[(2 * kp + 1) * 4];
            u64x2 wlo = wr[0], whi = wr[1];
            u64 tA = mul2(xA[0], wlo.x); fma2(tA, xA[1], wlo.y);
            fma2(tA, xA[2], whi.x); fma2(tA, xA[3], whi.y);
            u64 tB = mul2(xB[0], wlo.x); fma2(tB, xB[1], wlo.y);
            fma2(tB, xB[2], whi.x); fma2(tB, xB[3], whi.y);
            fma2(mA, rbA, tA); fma2(mB, rbB, tB);
        }
    }

    float m0, m1;
    unpack2(mA, m0, m1);
    if (v0) red_add_v2(out + 2 * d0, m0, m1);
    unpack2(mB, m0, m1);
    if (v1) red_add_v2(out + 2 * d1, m0, m1);
}

// ============================================================================
extern "C" void kernel_launch(void* const* d_in, const int* in_sizes, int n_in,
                              void* d_out, int out_size)
{
    const float* pos     = (const float*)d_in[0];
    const float* feat    = (const float*)d_in[1];
    const int*   esrc    = (const int*)  d_in[2];
    const int*   edst    = (const int*)  d_in[3];
    const float* fc1_w1  = (const float*)d_in[4];
    const float* fc1_w2  = (const float*)d_in[5];
    const float* core_w1 = (const float*)d_in[6];   // [3,3,16]
    const float* core_w2 = (const float*)d_in[7];   // [3,16,48]
    const float* fc3_w1  = (const float*)d_in[8];
    const float* fc3_w2  = (const float*)d_in[9];
    const float* conv_w  = (const float*)d_in[10];
    const float* conv_b  = (const float*)d_in[11];
    float* out = (float*)d_out;

    int E = in_sizes[2];
    int n = in_sizes[0] / 3;

    float4 *xA, *xB, *xC;
    cudaGetSymbolAddress((void**)&xA, g_xA);
    cudaGetSymbolAddress((void**)&xB, g_xB);
    cudaGetSymbolAddress((void**)&xC, g_xC);

    int eb = (E + 255) / 256;   // 256 edges per 128-thread block
    int nb = (n + 255) / 256;

    mprep_kernel<<<1, 128>>>(fc3_w2, conv_w);
    prep_kernel<<<nb, 256>>>(pos, feat, conv_b, out, n);

    conv1_kernel<<<eb, 128>>>(esrc, edst, fc1_w1, fc1_w2, xA, E);
    // core1: A->B, zero C for core2's output
    core_kernel<<<eb, 128>>>(esrc, edst, core_w1 + 0,  core_w2 + 0,    xA, xB, xC, n, E);
    // core2: B->C, zero A for core3's output
    core_kernel<<<eb, 128>>>(esrc, edst, core_w1 + 48, core_w2 + 768,  xB, xC, xA, n, E);
    // core3: C->A
    core_kernel<<<eb, 128>>>(esrc, edst, core_w1 + 96, core_w2 + 1536, xC, xA, (float4*)0, 0, E);

    conv3_kernel<<<eb, 128>>>(esrc, edst, fc3_w1, xA, out, E);
}

// round 9
// speedup vs baseline: 2.2237x; 1.2362x over previous
#include <cuda_runtime.h>
#include <math.h>

#define N_NODES_MAX 100000
#define N_EDGES_MAX 1600000

typedef unsigned long long u64;
typedef ulonglong2 u64x2;

// -------- scratch (static __device__; no allocation at launch time) --------
__device__ float4 g_emb4[N_EDGES_MAX];     // (em0, em1, em2, unused)
__device__ float4 g_pos4[N_NODES_MAX];
__device__ float4 g_feat4[N_NODES_MAX];
__device__ float4 g_xA[N_NODES_MAX];
__device__ float4 g_xB[N_NODES_MAX];
__device__ float4 g_xC[N_NODES_MAX];

// -------- packed weights: staged in __device__, copied to __constant__ -----
struct __align__(16) CW {
    u64 w1[5][32];     // [pass][kp*4 + i], i<3 valid; pass: 0=conv1,1..3=core,4=conv3
    u64 c1[96];        // conv1 W2 [k*6 + jp], C1 folded
    u64 core[3][128];  // core W2 [p][k*8 + jp], CCORE folded
    u64 m[64];         // conv3 fused M [k*4 + u] = (M[k,u,0], M[k,u,1]), CCORE folded
};
__device__ CW g_stage;
__constant__ CW cw;

// -------- constants (all e3nn normalization folded) --------
#define EMBC  (1.14136f * 7.38905609893065f * 1.7320508075688772f)
#define C1    (1.41421356237f / 48.0f)
#define CCORE (1.41421356237f / (1.7320508075688772f * 32.0f))

// -------- packed f32x2 helpers --------
__device__ __forceinline__ u64 pack2(float x, float y) {
    u64 r; asm("mov.b64 %0, {%1, %2};" : "=l"(r) : "f"(x), "f"(y)); return r;
}
__device__ __forceinline__ void unpack2(u64 v, float& x, float& y) {
    asm("mov.b64 {%0, %1}, %2;" : "=f"(x), "=f"(y) : "l"(v));
}
__device__ __forceinline__ void fma2(u64& d, u64 a, u64 b) {
    asm("fma.rn.f32x2 %0, %1, %2, %0;" : "+l"(d) : "l"(a), "l"(b));
}
__device__ __forceinline__ u64 mul2(u64 a, u64 b) {
    u64 d; asm("mul.rn.f32x2 %0, %1, %2;" : "=l"(d) : "l"(a), "l"(b)); return d;
}

// -------- vectorized global reductions (sm_90+) --------
__device__ __forceinline__ void red_add_v4(float4* addr, float a, float b, float c, float d) {
    asm volatile("red.global.add.v4.f32 [%0], {%1, %2, %3, %4};"
                 :: "l"(addr), "f"(a), "f"(b), "f"(c), "f"(d) : "memory");
}
__device__ __forceinline__ void red_add_v2(float* addr, float a, float b) {
    asm volatile("red.global.add.v2.f32 [%0], {%1, %2};"
                 :: "l"(addr), "f"(a), "f"(b) : "memory");
}

// ============================================================================
// weight prep: pack/fold everything into g_stage (then memcpy'd to cw)
__global__ void wprep_kernel(
    const float* __restrict__ fc1_w1, const float* __restrict__ fc1_w2,
    const float* __restrict__ core_w1, const float* __restrict__ core_w2,
    const float* __restrict__ fc3_w1, const float* __restrict__ fc3_w2,
    const float* __restrict__ conv_w)
{
    int t = threadIdx.x;   // 128
    if (t < 32) {
        int kp = t >> 2, i = t & 3;
#pragma unroll
        for (int pp = 0; pp < 5; pp++) {
            const float* src = (pp == 0) ? fc1_w1 : (pp <= 3 ? core_w1 + (pp - 1) * 48 : fc3_w1);
            u64 v = 0ull;
            if (i < 3) v = pack2(src[i * 16 + 2 * kp], src[i * 16 + 2 * kp + 1]);
            g_stage.w1[pp][t] = v;
        }
    }
    if (t < 96) {
        int k = t / 6, jp = t % 6;
        g_stage.c1[t] = pack2(C1 * fc1_w2[k * 12 + 2 * jp], C1 * fc1_w2[k * 12 + 2 * jp + 1]);
    }
    {
        int k = t >> 3, jp = t & 7;
#pragma unroll
        for (int p = 0; p < 3; p++)
            g_stage.core[p][t] = pack2(CCORE * core_w2[p * 768 + k * 48 + 2 * jp],
                                       CCORE * core_w2[p * 768 + k * 48 + 2 * jp + 1]);
    }
    if (t < 64) {
        int k = t >> 2, u = t & 3;
        float s0 = 0.f, s1 = 0.f;
#pragma unroll
        for (int w = 0; w < 16; w++) {
            float f = fc3_w2[k * 64 + u * 16 + w];
            s0 += f * conv_w[w];
            s1 += f * conv_w[16 + w];
        }
        g_stage.m[t] = pack2(CCORE * s0, CCORE * s1);
    }
}

// ============================================================================
// prep: pack pos/feat into float4 tables, zero xA/xB, write bias into out
__global__ void __launch_bounds__(256) prep_kernel(
    const float* __restrict__ pos, const float* __restrict__ feat,
    const float* __restrict__ conv_b, float* __restrict__ out, int n)
{
    int i = blockIdx.x * 256 + threadIdx.x;
    if (i >= n) return;
    g_pos4[i]  = make_float4(pos[3 * i], pos[3 * i + 1], pos[3 * i + 2], 0.f);
    g_feat4[i] = make_float4(feat[3 * i], feat[3 * i + 1], feat[3 * i + 2], 0.f);
    g_xA[i] = make_float4(0.f, 0.f, 0.f, 0.f);
    g_xB[i] = make_float4(0.f, 0.f, 0.f, 0.f);
    ((float2*)out)[i] = make_float2(conv_b[0], conv_b[1]);
}

// r pair for two edges at slice kp from __constant__ W1 (LDC path, no L1):
#define R_PAIRS(W1P, kp)                                                        \
    u64x2 wi01 = *(const u64x2*)&(W1P)[(kp) * 4];                               \
    u64 wi2 = (W1P)[(kp) * 4 + 2];                                              \
    u64 vA = mul2(eA0, wi01.x); fma2(vA, eA1, wi01.y); fma2(vA, eA2, wi2);      \
    u64 vB = mul2(eB0, wi01.x); fma2(vB, eB1, wi01.y); fma2(vB, eB2, wi2);      \
    float a0, a1, b0, b1;                                                       \
    unpack2(vA, a0, a1); unpack2(vB, b0, b1);                                   \
    a0 = fmaxf(a0, 0.f); a1 = fmaxf(a1, 0.f);                                   \
    b0 = fmaxf(b0, 0.f); b1 = fmaxf(b1, 0.f);                                   \
    u64 raA = pack2(a0, a0), rbA = pack2(a1, a1);                               \
    u64 raB = pack2(b0, b0), rbB = pack2(b1, b1);

// ============================================================================
// conv1: 2 edges/thread, t-form, constant weights; emb precompute + scatter
__global__ void __launch_bounds__(128, 7) conv1_kernel(
    const int* __restrict__ esrc, const int* __restrict__ edst,
    float4* __restrict__ xout, int E)
{
    int t = threadIdx.x;
    int base = blockIdx.x * 256;
    int e0 = base + t, e1 = base + 128 + t;
    bool v0 = e0 < E, v1 = e1 < E;
    int s0 = 0, d0 = 0, s1 = 0, d1 = 0;
    if (v0) { s0 = esrc[e0]; d0 = edst[e0]; }
    if (v1) { s1 = esrc[e1]; d1 = edst[e1]; }

    float4 ps0 = g_pos4[s0], pd0 = g_pos4[d0], f0 = g_feat4[s0];
    float4 ps1 = g_pos4[s1], pd1 = g_pos4[d1], f1 = g_feat4[s1];

    float emA[3], emB[3];
    {
        float dx = pd0.x - ps0.x, dy = pd0.y - ps0.y, dz = pd0.z - ps0.z;
        float dist = sqrtf(dx * dx + dy * dy + dz * dz);
#pragma unroll
        for (int i = 0; i < 3; i++) {
            float tt = (dist - 0.75f * (float)(i + 1)) * (1.0f / 0.75f);
            float q = 1.0f - tt * tt;
            emA[i] = (q > 0.0f) ? EMBC * __expf(__fdividef(-2.0f, q)) : 0.0f;
        }
    }
    {
        float dx = pd1.x - ps1.x, dy = pd1.y - ps1.y, dz = pd1.z - ps1.z;
        float dist = sqrtf(dx * dx + dy * dy + dz * dz);
#pragma unroll
        for (int i = 0; i < 3; i++) {
            float tt = (dist - 0.75f * (float)(i + 1)) * (1.0f / 0.75f);
            float q = 1.0f - tt * tt;
            emB[i] = (q > 0.0f) ? EMBC * __expf(__fdividef(-2.0f, q)) : 0.0f;
        }
    }
    if (v0) g_emb4[e0] = make_float4(emA[0], emA[1], emA[2], 0.f);
    if (v1) g_emb4[e1] = make_float4(emB[0], emB[1], emB[2], 0.f);

    u64 eA0 = pack2(emA[0], emA[0]), eA1 = pack2(emA[1], emA[1]), eA2 = pack2(emA[2], emA[2]);
    u64 eB0 = pack2(emB[0], emB[0]), eB1 = pack2(emB[1], emB[1]), eB2 = pack2(emB[2], emB[2]);
    u64 xA[3] = { pack2(f0.x, f0.x), pack2(f0.y, f0.y), pack2(f0.z, f0.z) };
    u64 xB[3] = { pack2(f1.x, f1.x), pack2(f1.y, f1.y), pack2(f1.z, f1.z) };

    u64 mA01 = 0ull, mA23 = 0ull, mB01 = 0ull, mB23 = 0ull;
#pragma unroll
    for (int kp = 0; kp < 8; kp++) {
        R_PAIRS(cw.w1[0], kp)
        {   // k = 2kp
            const u64x2* wr = (const u64x2*)&cw.c1[(2 * kp) * 6];
            u64 tA01, tA23, tB01, tB23;
#pragma unroll
            for (int u = 0; u < 3; u++) {
                u64x2 w = wr[u];
                if (u == 0) {
                    tA01 = mul2(xA[0], w.x); tA23 = mul2(xA[0], w.y);
                    tB01 = mul2(xB[0], w.x); tB23 = mul2(xB[0], w.y);
                } else {
                    fma2(tA01, xA[u], w.x); fma2(tA23, xA[u], w.y);
                    fma2(tB01, xB[u], w.x); fma2(tB23, xB[u], w.y);
                }
            }
            fma2(mA01, raA, tA01); fma2(mA23, raA, tA23);
            fma2(mB01, raB, tB01); fma2(mB23, raB, tB23);
        }
        {   // k = 2kp+1
            const u64x2* wr = (const u64x2*)&cw.c1[(2 * kp + 1) * 6];
            u64 tA01, tA23, tB01, tB23;
#pragma unroll
            for (int u = 0; u < 3; u++) {
                u64x2 w = wr[u];
                if (u == 0) {
                    tA01 = mul2(xA[0], w.x); tA23 = mul2(xA[0], w.y);
                    tB01 = mul2(xB[0], w.x); tB23 = mul2(xB[0], w.y);
                } else {
                    fma2(tA01, xA[u], w.x); fma2(tA23, xA[u], w.y);
                    fma2(tB01, xB[u], w.x); fma2(tB23, xB[u], w.y);
                }
            }
            fma2(mA01, rbA, tA01); fma2(mA23, rbA, tA23);
            fma2(mB01, rbB, tB01); fma2(mB23, rbB, tB23);
        }
    }

    float m0, m1, m2, m3;
    unpack2(mA01, m0, m1); unpack2(mA23, m2, m3);
    if (v0) red_add_v4(&xout[d0], m0, m1, m2, m3);
    unpack2(mB01, m0, m1); unpack2(mB23, m2, m3);
    if (v1) red_add_v4(&xout[d1], m0, m1, m2, m3);
}

// ============================================================================
// core conv: 2 edges/thread, t-form, constant weights; zeroes zbuf
__global__ void __launch_bounds__(128, 8) core_kernel(
    const int* __restrict__ esrc, const int* __restrict__ edst, int p,
    const float4* __restrict__ xin, float4* __restrict__ xout,
    float4* __restrict__ zbuf, int zn, int E)
{
    int t = threadIdx.x;
    int zi = blockIdx.x * 128 + t;
    if (zi < zn) zbuf[zi] = make_float4(0.f, 0.f, 0.f, 0.f);

    int base = blockIdx.x * 256;
    int e0 = base + t, e1 = base + 128 + t;
    bool v0 = e0 < E, v1 = e1 < E;
    int s0 = 0, d0 = 0, s1 = 0, d1 = 0;
    if (v0) { s0 = esrc[e0]; d0 = edst[e0]; }
    if (v1) { s1 = esrc[e1]; d1 = edst[e1]; }

    float4 x0 = xin[s0];
    float4 x1 = xin[s1];
    float4 emA = g_emb4[v0 ? e0 : 0];
    float4 emB = g_emb4[v1 ? e1 : 0];

    int wp = 1 + p;
    u64 eA0 = pack2(emA.x, emA.x), eA1 = pack2(emA.y, emA.y), eA2 = pack2(emA.z, emA.z);
    u64 eB0 = pack2(emB.x, emB.x), eB1 = pack2(emB.y, emB.y), eB2 = pack2(emB.z, emB.z);
    u64 xA[4] = { pack2(x0.x, x0.x), pack2(x0.y, x0.y), pack2(x0.z, x0.z), pack2(x0.w, x0.w) };
    u64 xB[4] = { pack2(x1.x, x1.x), pack2(x1.y, x1.y), pack2(x1.z, x1.z), pack2(x1.w, x1.w) };

    u64 mA01 = 0ull, mA23 = 0ull, mB01 = 0ull, mB23 = 0ull;
#pragma unroll
    for (int kp = 0; kp < 8; kp++) {
        R_PAIRS(cw.w1[wp], kp)
        {   // k = 2kp
            const u64x2* wr = (const u64x2*)&cw.core[p][(2 * kp) * 8];
            u64 tA01, tA23, tB01, tB23;
#pragma unroll
            for (int u = 0; u < 4; u++) {
                u64x2 w = wr[u];
                if (u == 0) {
                    tA01 = mul2(xA[0], w.x); tA23 = mul2(xA[0], w.y);
                    tB01 = mul2(xB[0], w.x); tB23 = mul2(xB[0], w.y);
                } else {
                    fma2(tA01, xA[u], w.x); fma2(tA23, xA[u], w.y);
                    fma2(tB01, xB[u], w.x); fma2(tB23, xB[u], w.y);
                }
            }
            fma2(mA01, raA, tA01); fma2(mA23, raA, tA23);
            fma2(mB01, raB, tB01); fma2(mB23, raB, tB23);
        }
        {   // k = 2kp+1
            const u64x2* wr = (const u64x2*)&cw.core[p][(2 * kp + 1) * 8];
            u64 tA01, tA23, tB01, tB23;
#pragma unroll
            for (int u = 0; u < 4; u++) {
                u64x2 w = wr[u];
                if (u == 0) {
                    tA01 = mul2(xA[0], w.x); tA23 = mul2(xA[0], w.y);
                    tB01 = mul2(xB[0], w.x); tB23 = mul2(xB[0], w.y);
                } else {
                    fma2(tA01, xA[u], w.x); fma2(tA23, xA[u], w.y);
                    fma2(tB01, xB[u], w.x); fma2(tB23, xB[u], w.y);
                }
            }
            fma2(mA01, rbA, tA01); fma2(mA23, rbA, tA23);
            fma2(mB01, rbB, tB01); fma2(mB23, rbB, tB23);
        }
    }

    float m0, m1, m2, m3;
    unpack2(mA01, m0, m1); unpack2(mA23, m2, m3);
    if (v0) red_add_v4(&xout[d0], m0, m1, m2, m3);
    unpack2(mB01, m0, m1); unpack2(mB23, m2, m3);
    if (v1) red_add_v4(&xout[d1], m0, m1, m2, m3);
}

// ============================================================================
// conv3 fused with Conv1d(16,2,1): 2 edges/thread, t-form, constant weights
__global__ void __launch_bounds__(128, 8) conv3_kernel(
    const int* __restrict__ esrc, const int* __restrict__ edst,
    const float4* __restrict__ xin, float* __restrict__ out, int E)
{
    int t = threadIdx.x;
    int base = blockIdx.x * 256;
    int e0 = base + t, e1 = base + 128 + t;
    bool v0 = e0 < E, v1 = e1 < E;
    int s0 = 0, d0 = 0, s1 = 0, d1 = 0;
    if (v0) { s0 = esrc[e0]; d0 = edst[e0]; }
    if (v1) { s1 = esrc[e1]; d1 = edst[e1]; }

    float4 x0 = xin[s0];
    float4 x1 = xin[s1];
    float4 emA = g_emb4[v0 ? e0 : 0];
    float4 emB = g_emb4[v1 ? e1 : 0];

    u64 eA0 = pack2(emA.x, emA.x), eA1 = pack2(emA.y, emA.y), eA2 = pack2(emA.z, emA.z);
    u64 eB0 = pack2(emB.x, emB.x), eB1 = pack2(emB.y, emB.y), eB2 = pack2(emB.z, emB.z);
    u64 xA[4] = { pack2(x0.x, x0.x), pack2(x0.y, x0.y), pack2(x0.z, x0.z), pack2(x0.w, x0.w) };
    u64 xB[4] = { pack2(x1.x, x1.x), pack2(x1.y, x1.y), pack2(x1.z, x1.z), pack2(x1.w, x1.w) };

    u64 mA = 0ull, mB = 0ull;   // (c0, c1) per edge
#pragma unroll
    for (int kp = 0; kp < 8; kp++) {
        R_PAIRS(cw.w1[4], kp)
        {   // k = 2kp
            const u64x2* wr = (const u64x2*)&cw.m[(2 * kp) * 4];
            u64x2 wlo = wr[0], whi = wr[1];
            u64 tA = mul2(xA[0], wlo.x); fma2(tA, xA[1], wlo.y);
            fma2(tA, xA[2], whi.x); fma2(tA, xA[3], whi.y);
            u64 tB = mul2(xB[0], wlo.x); fma2(tB, xB[1], wlo.y);
            fma2(tB, xB[2], whi.x); fma2(tB, xB[3], whi.y);
            fma2(mA, raA, tA); fma2(mB, raB, tB);
        }
        {   // k = 2kp+1
            const u64x2* wr = (const u64x2*)&cw.m[(2 * kp + 1) * 4];
            u64x2 wlo = wr[0], whi = wr[1];
            u64 tA = mul2(xA[0], wlo.x); fma2(tA, xA[1], wlo.y);
            fma2(tA, xA[2], whi.x); fma2(tA, xA[3], whi.y);
            u64 tB = mul2(xB[0], wlo.x); fma2(tB, xB[1], wlo.y);
            fma2(tB, xB[2], whi.x); fma2(tB, xB[3], whi.y);
            fma2(mA, rbA, tA); fma2(mB, rbB, tB);
        }
    }

    float m0, m1;
    unpack2(mA, m0, m1);
    if (v0) red_add_v2(out + 2 * d0, m0, m1);
    unpack2(mB, m0, m1);
    if (v1) red_add_v2(out + 2 * d1, m0, m1);
}

// ============================================================================
extern "C" void kernel_launch(void* const* d_in, const int* in_sizes, int n_in,
                              void* d_out, int out_size)
{
    const float* pos     = (const float*)d_in[0];
    const float* feat    = (const float*)d_in[1];
    const int*   esrc    = (const int*)  d_in[2];
    const int*   edst    = (const int*)  d_in[3];
    const float* fc1_w1  = (const float*)d_in[4];
    const float* fc1_w2  = (const float*)d_in[5];
    const float* core_w1 = (const float*)d_in[6];   // [3,3,16]
    const float* core_w2 = (const float*)d_in[7];   // [3,16,48]
    const float* fc3_w1  = (const float*)d_in[8];
    const float* fc3_w2  = (const float*)d_in[9];
    const float* conv_w  = (const float*)d_in[10];
    const float* conv_b  = (const float*)d_in[11];
    float* out = (float*)d_out;

    int E = in_sizes[2];
    int n = in_sizes[0] / 3;

    float4 *xA, *xB, *xC;
    void* stg;
    cudaGetSymbolAddress((void**)&xA, g_xA);
    cudaGetSymbolAddress((void**)&xB, g_xB);
    cudaGetSymbolAddress((void**)&xC, g_xC);
    cudaGetSymbolAddress(&stg, g_stage);

    int eb = (E + 255) / 256;   // 256 edges per 128-thread block
    int nb = (n + 255) / 256;

    // pack + fold weights, then stage them into the constant bank (D2D, graph-legal)
    wprep_kernel<<<1, 128>>>(fc1_w1, fc1_w2, core_w1, core_w2, fc3_w1, fc3_w2, conv_w);
    cudaMemcpyToSymbolAsync(cw, stg, sizeof(CW), 0, cudaMemcpyDeviceToDevice, 0);

    prep_kernel<<<nb, 256>>>(pos, feat, conv_b, out, n);

    conv1_kernel<<<eb, 128>>>(esrc, edst, xA, E);
    // core1: A->B, zero C for core2's output
    core_kernel<<<eb, 128>>>(esrc, edst, 0, xA, xB, xC, n, E);
    // core2: B->C, zero A for core3's output
    core_kernel<<<eb, 128>>>(esrc, edst, 1, xB, xC, xA, n, E);
    // core3: C->A
    core_kernel<<<eb, 128>>>(esrc, edst, 2, xC, xA, (float4*)0, 0, E);

    conv3_kernel<<<eb, 128>>>(esrc, edst, xA, out, E);
}

// round 12
// speedup vs baseline: 2.3428x; 1.0535x over previous
#include <cuda_runtime.h>
#include <math.h>

#define N_NODES_MAX 100000
#define N_EDGES_MAX 1600000

typedef unsigned long long u64;
typedef ulonglong2 u64x2;

// -------- scratch (static __device__; no allocation at launch time) --------
__device__ float4 g_emb4[N_EDGES_MAX];     // (em0, em1, em2, unused)
__device__ float4 g_pos4[N_NODES_MAX];
__device__ float4 g_feat4[N_NODES_MAX];
__device__ float4 g_xA[N_NODES_MAX];
__device__ float4 g_xB[N_NODES_MAX];
__device__ float4 g_xC[N_NODES_MAX];

// -------- packed weights: staged in __device__, copied to __constant__ -----
struct __align__(16) CW {
    u64 w1[5][32];     // [pass][kp*4 + i], i<3 valid; pass: 0=conv1,1..3=core,4=conv3
    u64 c1[96];        // conv1 W2 [k*6 + jp], C1 folded
    u64 core[3][128];  // core W2 [p][k*8 + jp], CCORE folded
    u64 m[64];         // conv3 fused M [k*4 + u] = (M[k,u,0], M[k,u,1]), CCORE folded
};
__device__ CW g_stage;
__constant__ CW cw;

// -------- constants (all e3nn normalization folded) --------
#define EMBC  (1.14136f * 7.38905609893065f * 1.7320508075688772f)
#define C1    (1.41421356237f / 48.0f)
#define CCORE (1.41421356237f / (1.7320508075688772f * 32.0f))

// -------- packed f32x2 helpers --------
__device__ __forceinline__ u64 pack2(float x, float y) {
    u64 r; asm("mov.b64 %0, {%1, %2};" : "=l"(r) : "f"(x), "f"(y)); return r;
}
__device__ __forceinline__ void unpack2(u64 v, float& x, float& y) {
    asm("mov.b64 {%0, %1}, %2;" : "=f"(x), "=f"(y) : "l"(v));
}
__device__ __forceinline__ void fma2(u64& d, u64 a, u64 b) {
    asm("fma.rn.f32x2 %0, %1, %2, %0;" : "+l"(d) : "l"(a), "l"(b));
}
__device__ __forceinline__ u64 mul2(u64 a, u64 b) {
    u64 d; asm("mul.rn.f32x2 %0, %1, %2;" : "=l"(d) : "l"(a), "l"(b)); return d;
}

// -------- vectorized global reductions (sm_90+) --------
__device__ __forceinline__ void red_add_v4(float4* addr, float a, float b, float c, float d) {
    asm volatile("red.global.add.v4.f32 [%0], {%1, %2, %3, %4};"
                 :: "l"(addr), "f"(a), "f"(b), "f"(c), "f"(d) : "memory");
}
__device__ __forceinline__ void red_add_v2(float* addr, float a, float b) {
    asm volatile("red.global.add.v2.f32 [%0], {%1, %2};"
                 :: "l"(addr), "f"(a), "f"(b) : "memory");
}

// ============================================================================
// weight prep: pack/fold everything into g_stage (then memcpy'd to cw)
__global__ void wprep_kernel(
    const float* __restrict__ fc1_w1, const float* __restrict__ fc1_w2,
    const float* __restrict__ core_w1, const float* __restrict__ core_w2,
    const float* __restrict__ fc3_w1, const float* __restrict__ fc3_w2,
    const float* __restrict__ conv_w)
{
    int t = threadIdx.x;   // 128
    if (t < 32) {
        int kp = t >> 2, i = t & 3;
#pragma unroll
        for (int pp = 0; pp < 5; pp++) {
            const float* src = (pp == 0) ? fc1_w1 : (pp <= 3 ? core_w1 + (pp - 1) * 48 : fc3_w1);
            u64 v = 0ull;
            if (i < 3) v = pack2(src[i * 16 + 2 * kp], src[i * 16 + 2 * kp + 1]);
            g_stage.w1[pp][t] = v;
        }
    }
    if (t < 96) {
        int k = t / 6, jp = t % 6;
        g_stage.c1[t] = pack2(C1 * fc1_w2[k * 12 + 2 * jp], C1 * fc1_w2[k * 12 + 2 * jp + 1]);
    }
    {
        int k = t >> 3, jp = t & 7;
#pragma unroll
        for (int p = 0; p < 3; p++)
            g_stage.core[p][t] = pack2(CCORE * core_w2[p * 768 + k * 48 + 2 * jp],
                                       CCORE * core_w2[p * 768 + k * 48 + 2 * jp + 1]);
    }
    if (t < 64) {
        int k = t >> 2, u = t & 3;
        float s0 = 0.f, s1 = 0.f;
#pragma unroll
        for (int w = 0; w < 16; w++) {
            float f = fc3_w2[k * 64 + u * 16 + w];
            s0 += f * conv_w[w];
            s1 += f * conv_w[16 + w];
        }
        g_stage.m[t] = pack2(CCORE * s0, CCORE * s1);
    }
}

// ============================================================================
// prep: pack pos/feat into float4 tables, zero xA/xB, write bias into out
__global__ void __launch_bounds__(256) prep_kernel(
    const float* __restrict__ pos, const float* __restrict__ feat,
    const float* __restrict__ conv_b, float* __restrict__ out, int n)
{
    int i = blockIdx.x * 256 + threadIdx.x;
    if (i >= n) return;
    g_pos4[i]  = make_float4(pos[3 * i], pos[3 * i + 1], pos[3 * i + 2], 0.f);
    g_feat4[i] = make_float4(feat[3 * i], feat[3 * i + 1], feat[3 * i + 2], 0.f);
    g_xA[i] = make_float4(0.f, 0.f, 0.f, 0.f);
    g_xB[i] = make_float4(0.f, 0.f, 0.f, 0.f);
    ((float2*)out)[i] = make_float2(conv_b[0], conv_b[1]);
}

// r pair for two edges at slice kp from __constant__ W1 (LDC path, no L1):
#define R_PAIRS(W1P, kp)                                                        \
    u64x2 wi01 = *(const u64x2*)&(W1P)[(kp) * 4];                               \
    u64 wi2 = (W1P)[(kp) * 4 + 2];                                              \
    u64 vA = mul2(eA0, wi01.x); fma2(vA, eA1, wi01.y); fma2(vA, eA2, wi2);      \
    u64 vB = mul2(eB0, wi01.x); fma2(vB, eB1, wi01.y); fma2(vB, eB2, wi2);      \
    float a0, a1, b0, b1;                                                       \
    unpack2(vA, a0, a1); unpack2(vB, b0, b1);                                   \
    a0 = fmaxf(a0, 0.f); a1 = fmaxf(a1, 0.f);                                   \
    b0 = fmaxf(b0, 0.f); b1 = fmaxf(b1, 0.f);                                   \
    u64 raA = pack2(a0, a0), rbA = pack2(a1, a1);                               \
    u64 raB = pack2(b0, b0), rbB = pack2(b1, b1);

// ============================================================================
// conv1: 2 edges/thread, acc-form, constant weights; emb precompute + scatter
__global__ void __launch_bounds__(128, 7) conv1_kernel(
    const int* __restrict__ esrc, const int* __restrict__ edst,
    float4* __restrict__ xout, int E)
{
    int t = threadIdx.x;
    int base = blockIdx.x * 256;
    int e0 = base + t, e1 = base + 128 + t;
    bool v0 = e0 < E, v1 = e1 < E;
    int s0 = 0, d0 = 0, s1 = 0, d1 = 0;
    if (v0) { s0 = esrc[e0]; d0 = edst[e0]; }
    if (v1) { s1 = esrc[e1]; d1 = edst[e1]; }

    float4 ps0 = g_pos4[s0], pd0 = g_pos4[d0], f0 = g_feat4[s0];
    float4 ps1 = g_pos4[s1], pd1 = g_pos4[d1], f1 = g_feat4[s1];

    float emA[3], emB[3];
    {
        float dx = pd0.x - ps0.x, dy = pd0.y - ps0.y, dz = pd0.z - ps0.z;
        float dist = sqrtf(dx * dx + dy * dy + dz * dz);
#pragma unroll
        for (int i = 0; i < 3; i++) {
            float tt = (dist - 0.75f * (float)(i + 1)) * (1.0f / 0.75f);
            float q = 1.0f - tt * tt;
            emA[i] = (q > 0.0f) ? EMBC * __expf(__fdividef(-2.0f, q)) : 0.0f;
        }
    }
    {
        float dx = pd1.x - ps1.x, dy = pd1.y - ps1.y, dz = pd1.z - ps1.z;
        float dist = sqrtf(dx * dx + dy * dy + dz * dz);
#pragma unroll
        for (int i = 0; i < 3; i++) {
            float tt = (dist - 0.75f * (float)(i + 1)) * (1.0f / 0.75f);
            float q = 1.0f - tt * tt;
            emB[i] = (q > 0.0f) ? EMBC * __expf(__fdividef(-2.0f, q)) : 0.0f;
        }
    }
    if (v0) g_emb4[e0] = make_float4(emA[0], emA[1], emA[2], 0.f);
    if (v1) g_emb4[e1] = make_float4(emB[0], emB[1], emB[2], 0.f);

    u64 eA0 = pack2(emA[0], emA[0]), eA1 = pack2(emA[1], emA[1]), eA2 = pack2(emA[2], emA[2]);
    u64 eB0 = pack2(emB[0], emB[0]), eB1 = pack2(emB[1], emB[1]), eB2 = pack2(emB[2], emB[2]);

    // G accumulators: [u*2 + wp], u<3
    u64 accA[6], accB[6];
#pragma unroll
    for (int j = 0; j < 6; j++) { accA[j] = 0ull; accB[j] = 0ull; }

#pragma unroll
    for (int kp = 0; kp < 8; kp++) {
        R_PAIRS(cw.w1[0], kp)
        const u64x2* wr0 = (const u64x2*)&cw.c1[(2 * kp) * 6];
        const u64x2* wr1 = (const u64x2*)&cw.c1[(2 * kp + 1) * 6];
#pragma unroll
        for (int q = 0; q < 3; q++) {
            u64x2 w = wr0[q];
            fma2(accA[2 * q], raA, w.x); fma2(accA[2 * q + 1], raA, w.y);
            fma2(accB[2 * q], raB, w.x); fma2(accB[2 * q + 1], raB, w.y);
        }
#pragma unroll
        for (int q = 0; q < 3; q++) {
            u64x2 w = wr1[q];
            fma2(accA[2 * q], rbA, w.x); fma2(accA[2 * q + 1], rbA, w.y);
            fma2(accB[2 * q], rbB, w.x); fma2(accB[2 * q + 1], rbB, w.y);
        }
    }

    {
        u64 xu0 = pack2(f0.x, f0.x), xu1 = pack2(f0.y, f0.y), xu2 = pack2(f0.z, f0.z);
        u64 m01 = mul2(xu0, accA[0]), m23 = mul2(xu0, accA[1]);
        fma2(m01, xu1, accA[2]); fma2(m23, xu1, accA[3]);
        fma2(m01, xu2, accA[4]); fma2(m23, xu2, accA[5]);
        float m0, m1, m2, m3;
        unpack2(m01, m0, m1); unpack2(m23, m2, m3);
        if (v0) red_add_v4(&xout[d0], m0, m1, m2, m3);
    }
    {
        u64 xu0 = pack2(f1.x, f1.x), xu1 = pack2(f1.y, f1.y), xu2 = pack2(f1.z, f1.z);
        u64 m01 = mul2(xu0, accB[0]), m23 = mul2(xu0, accB[1]);
        fma2(m01, xu1, accB[2]); fma2(m23, xu1, accB[3]);
        fma2(m01, xu2, accB[4]); fma2(m23, xu2, accB[5]);
        float m0, m1, m2, m3;
        unpack2(m01, m0, m1); unpack2(m23, m2, m3);
        if (v1) red_add_v4(&xout[d1], m0, m1, m2, m3);
    }
}

// ============================================================================
// core conv: 2 edges/thread, acc-form (G = sum_k r_k W2[k]), const weights
__global__ void __launch_bounds__(128, 7) core_kernel(
    const int* __restrict__ esrc, const int* __restrict__ edst, int p,
    const float4* __restrict__ xin, float4* __restrict__ xout,
    float4* __restrict__ zbuf, int zn, int E)
{
    int t = threadIdx.x;
    int zi = blockIdx.x * 128 + t;
    if (zi < zn) zbuf[zi] = make_float4(0.f, 0.f, 0.f, 0.f);

    int base = blockIdx.x * 256;
    int e0 = base + t, e1 = base + 128 + t;
    bool v0 = e0 < E, v1 = e1 < E;
    int s0 = 0, d0 = 0, s1 = 0, d1 = 0;
    if (v0) { s0 = esrc[e0]; d0 = edst[e0]; }
    if (v1) { s1 = esrc[e1]; d1 = edst[e1]; }

    float4 x0 = xin[s0];
    float4 x1 = xin[s1];
    float4 emA = g_emb4[v0 ? e0 : 0];
    float4 emB = g_emb4[v1 ? e1 : 0];

    int wp = 1 + p;
    u64 eA0 = pack2(emA.x, emA.x), eA1 = pack2(emA.y, emA.y), eA2 = pack2(emA.z, emA.z);
    u64 eB0 = pack2(emB.x, emB.x), eB1 = pack2(emB.y, emB.y), eB2 = pack2(emB.z, emB.z);

    // G accumulators: [u*2 + wp2] (pair over output w)
    u64 accA[8], accB[8];
#pragma unroll
    for (int j = 0; j < 8; j++) { accA[j] = 0ull; accB[j] = 0ull; }

#pragma unroll
    for (int kp = 0; kp < 8; kp++) {
        R_PAIRS(cw.w1[wp], kp)
        const u64x2* wr0 = (const u64x2*)&cw.core[p][(2 * kp) * 8];
        const u64x2* wr1 = (const u64x2*)&cw.core[p][(2 * kp + 1) * 8];
#pragma unroll
        for (int q = 0; q < 4; q++) {
            u64x2 w = wr0[q];
            fma2(accA[2 * q], raA, w.x); fma2(accA[2 * q + 1], raA, w.y);
            fma2(accB[2 * q], raB, w.x); fma2(accB[2 * q + 1], raB, w.y);
        }
#pragma unroll
        for (int q = 0; q < 4; q++) {
            u64x2 w = wr1[q];
            fma2(accA[2 * q], rbA, w.x); fma2(accA[2 * q + 1], rbA, w.y);
            fma2(accB[2 * q], rbB, w.x); fma2(accB[2 * q + 1], rbB, w.y);
        }
    }

    {
        u64 xu0 = pack2(x0.x, x0.x), xu1 = pack2(x0.y, x0.y);
        u64 xu2 = pack2(x0.z, x0.z), xu3 = pack2(x0.w, x0.w);
        u64 m01 = mul2(xu0, accA[0]), m23 = mul2(xu0, accA[1]);
        fma2(m01, xu1, accA[2]); fma2(m23, xu1, accA[3]);
        fma2(m01, xu2, accA[4]); fma2(m23, xu2, accA[5]);
        fma2(m01, xu3, accA[6]); fma2(m23, xu3, accA[7]);
        float m0, m1, m2, m3;
        unpack2(m01, m0, m1); unpack2(m23, m2, m3);
        if (v0) red_add_v4(&xout[d0], m0, m1, m2, m3);
    }
    {
        u64 xu0 = pack2(x1.x, x1.x), xu1 = pack2(x1.y, x1.y);
        u64 xu2 = pack2(x1.z, x1.z), xu3 = pack2(x1.w, x1.w);
        u64 m01 = mul2(xu0, accB[0]), m23 = mul2(xu0, accB[1]);
        fma2(m01, xu1, accB[2]); fma2(m23, xu1, accB[3]);
        fma2(m01, xu2, accB[4]); fma2(m23, xu2, accB[5]);
        fma2(m01, xu3, accB[6]); fma2(m23, xu3, accB[7]);
        float m0, m1, m2, m3;
        unpack2(m01, m0, m1); unpack2(m23, m2, m3);
        if (v1) red_add_v4(&xout[d1], m0, m1, m2, m3);
    }
}

// ============================================================================
// conv3 fused with Conv1d(16,2,1): 2 edges/thread, acc-form, const weights
__global__ void __launch_bounds__(128, 8) conv3_kernel(
    const int* __restrict__ esrc, const int* __restrict__ edst,
    const float4* __restrict__ xin, float* __restrict__ out, int E)
{
    int t = threadIdx.x;
    int base = blockIdx.x * 256;
    int e0 = base + t, e1 = base + 128 + t;
    bool v0 = e0 < E, v1 = e1 < E;
    int s0 = 0, d0 = 0, s1 = 0, d1 = 0;
    if (v0) { s0 = esrc[e0]; d0 = edst[e0]; }
    if (v1) { s1 = esrc[e1]; d1 = edst[e1]; }

    float4 x0 = xin[s0];
    float4 x1 = xin[s1];
    float4 emA = g_emb4[v0 ? e0 : 0];
    float4 emB = g_emb4[v1 ? e1 : 0];

    u64 eA0 = pack2(emA.x, emA.x), eA1 = pack2(emA.y, emA.y), eA2 = pack2(emA.z, emA.z);
    u64 eB0 = pack2(emB.x, emB.x), eB1 = pack2(emB.y, emB.y), eB2 = pack2(emB.z, emB.z);

    // G accumulators: [u] = pair over output channel c
    u64 accA[4], accB[4];
#pragma unroll
    for (int j = 0; j < 4; j++) { accA[j] = 0ull; accB[j] = 0ull; }

#pragma unroll
    for (int kp = 0; kp < 8; kp++) {
        R_PAIRS(cw.w1[4], kp)
        const u64x2* wr0 = (const u64x2*)&cw.m[(2 * kp) * 4];
        const u64x2* wr1 = (const u64x2*)&cw.m[(2 * kp + 1) * 4];
#pragma unroll
        for (int q = 0; q < 2; q++) {
            u64x2 w = wr0[q];
            fma2(accA[2 * q], raA, w.x); fma2(accA[2 * q + 1], raA, w.y);
            fma2(accB[2 * q], raB, w.x); fma2(accB[2 * q + 1], raB, w.y);
        }
#pragma unroll
        for (int q = 0; q < 2; q++) {
            u64x2 w = wr1[q];
            fma2(accA[2 * q], rbA, w.x); fma2(accA[2 * q + 1], rbA, w.y);
            fma2(accB[2 * q], rbB, w.x); fma2(accB[2 * q + 1], rbB, w.y);
        }
    }

    {
        u64 xu0 = pack2(x0.x, x0.x), xu1 = pack2(x0.y, x0.y);
        u64 xu2 = pack2(x0.z, x0.z), xu3 = pack2(x0.w, x0.w);
        u64 mc = mul2(xu0, accA[0]);
        fma2(mc, xu1, accA[1]); fma2(mc, xu2, accA[2]); fma2(mc, xu3, accA[3]);
        float m0, m1;
        unpack2(mc, m0, m1);
        if (v0) red_add_v2(out + 2 * d0, m0, m1);
    }
    {
        u64 xu0 = pack2(x1.x, x1.x), xu1 = pack2(x1.y, x1.y);
        u64 xu2 = pack2(x1.z, x1.z), xu3 = pack2(x1.w, x1.w);
        u64 mc = mul2(xu0, accB[0]);
        fma2(mc, xu1, accB[1]); fma2(mc, xu2, accB[2]); fma2(mc, xu3, accB[3]);
        float m0, m1;
        unpack2(mc, m0, m1);
        if (v1) red_add_v2(out + 2 * d1, m0, m1);
    }
}

// ============================================================================
extern "C" void kernel_launch(void* const* d_in, const int* in_sizes, int n_in,
                              void* d_out, int out_size)
{
    const float* pos     = (const float*)d_in[0];
    const float* feat    = (const float*)d_in[1];
    const int*   esrc    = (const int*)  d_in[2];
    const int*   edst    = (const int*)  d_in[3];
    const float* fc1_w1  = (const float*)d_in[4];
    const float* fc1_w2  = (const float*)d_in[5];
    const float* core_w1 = (const float*)d_in[6];   // [3,3,16]
    const float* core_w2 = (const float*)d_in[7];   // [3,16,48]
    const float* fc3_w1  = (const float*)d_in[8];
    const float* fc3_w2  = (const float*)d_in[9];
    const float* conv_w  = (const float*)d_in[10];
    const float* conv_b  = (const float*)d_in[11];
    float* out = (float*)d_out;

    int E = in_sizes[2];
    int n = in_sizes[0] / 3;

    float4 *xA, *xB, *xC;
    void* stg;
    cudaGetSymbolAddress((void**)&xA, g_xA);
    cudaGetSymbolAddress((void**)&xB, g_xB);
    cudaGetSymbolAddress((void**)&xC, g_xC);
    cudaGetSymbolAddress(&stg, g_stage);

    int eb = (E + 255) / 256;   // 256 edges per 128-thread block
    int nb = (n + 255) / 256;

    // pack + fold weights, then stage them into the constant bank (D2D, graph-legal)
    wprep_kernel<<<1, 128>>>(fc1_w1, fc1_w2, core_w1, core_w2, fc3_w1, fc3_w2, conv_w);
    cudaMemcpyToSymbolAsync(cw, stg, sizeof(CW), 0, cudaMemcpyDeviceToDevice, 0);

    prep_kernel<<<nb, 256>>>(pos, feat, conv_b, out, n);

    conv1_kernel<<<eb, 128>>>(esrc, edst, xA, E);
    // core1: A->B, zero C for core2's output
    core_kernel<<<eb, 128>>>(esrc, edst, 0, xA, xB, xC, n, E);
    // core2: B->C, zero A for core3's output
    core_kernel<<<eb, 128>>>(esrc, edst, 1, xB, xC, xA, n, E);
    // core3: C->A
    core_kernel<<<eb, 128>>>(esrc, edst, 2, xC, xA, (float4*)0, 0, E);

    conv3_kernel<<<eb, 128>>>(esrc, edst, xA, out, E);
}